// round 12
// baseline (speedup 1.0000x reference)
// R12: resubmission of R11 (span 128x128 on S=5 dyn-smem pipeline).
// "container failed twice" = known infra-side failure (R0 empty stub; R5/R6 source passed at R7).
#include <cuda_runtime.h>
#include <cuda_bf16.h>
#include <math.h>
#include <stdint.h>

// Problem constants
#define Bn   8
#define Ln   256
#define Dn   1024
#define An   64
#define Vn   128
#define En   256
#define Gn   2048
#define Wn   255
#define NEGV (-1000.0f)

// bf16 pack/unpack
__device__ __forceinline__ uint32_t pk2(float a, float b) {
    __nv_bfloat162 h; h.x = __float2bfloat16(a); h.y = __float2bfloat16(b);
    return *reinterpret_cast<uint32_t*>(&h);
}
__device__ __forceinline__ float2 upk2(uint32_t u) {
    __nv_bfloat162 h = *reinterpret_cast<__nv_bfloat162*>(&u);
    return __bfloat1622float2(h);
}
__device__ __forceinline__ uint32_t sm_u32(const void* p) {
    uint32_t a;
    asm("{ .reg .u64 t; cvta.to.shared.u64 t, %1; cvt.u32.u64 %0, t; }" : "=r"(a) : "l"(p));
    return a;
}

// warp mma: D(16x8,f32) += A(16x16,bf16,row) * B(16x8,bf16,col)
__device__ __forceinline__ void mma16816(float d[4], uint32_t a0, uint32_t a1,
                                         uint32_t a2, uint32_t a3,
                                         uint32_t b0, uint32_t b1) {
    asm volatile(
        "mma.sync.aligned.m16n8k16.row.col.f32.bf16.bf16.f32 "
        "{%0,%1,%2,%3}, {%4,%5,%6,%7}, {%8,%9}, {%0,%1,%2,%3};\n"
        : "+f"(d[0]), "+f"(d[1]), "+f"(d[2]), "+f"(d[3])
        : "r"(a0), "r"(a1), "r"(a2), "r"(a3), "r"(b0), "r"(b1));
}
__device__ __forceinline__ void ldsm_x4(uint32_t r[4], uint32_t addr) {
    asm volatile("ldmatrix.sync.aligned.m8n8.x4.shared.b16 {%0,%1,%2,%3}, [%4];\n"
                 : "=r"(r[0]), "=r"(r[1]), "=r"(r[2]), "=r"(r[3]) : "r"(addr));
}
__device__ __forceinline__ void cp16(uint32_t s_dst, const void* g_src) {
    asm volatile("cp.async.cg.shared.global [%0], [%1], 16;\n" :: "r"(s_dst), "l"(g_src));
}
#define CP_COMMIT() asm volatile("cp.async.commit_group;\n" ::: "memory")

// ===================== device scratch =====================
__device__ __align__(16) __nv_bfloat16 g_reprs_b[Bn * Ln * Dn];   // 4 MB
__device__ __align__(16) __nv_bfloat16 g_word_b[Bn * Wn * Dn];    // ~4 MB
__device__ __align__(16) __nv_bfloat16 g_Wp1b[En * 2 * Dn];       // 1 MB
__device__ __align__(16) __nv_bfloat16 g_Wt[Dn * Dn];             // W^T bf16, 2 MB
__device__ __align__(16) __nv_bfloat16 g_Tb[Bn * Ln * Dn];        // T bf16, 4 MB
__device__ float g_Tbias[Bn * Ln];                                 // T[:,1024] fp32
__device__ __align__(16) __nv_bfloat16 g_goldb[Bn * An * 2 * Dn]; // 2 MB
__device__ float g_h1p[8 * 512 * 256];                             // h1 split-K partials
__device__ __align__(16) uint32_t g_bitmap[Bn * Ln * Ln / 32];     // gold bitmap, 64 KB
__device__ float g_span_sum[24];
__device__ float g_span_cnt2[24];
__device__ float g_ce_part[512];

// ===================== merged prelude =====================
#define N_REPRS (Bn * Ln * Dn)        // 2097152
#define N_WORD  (Bn * Wn * Dn)        // 2088960
#define N_WP1   (En * 2 * Dn)         // 524288
#define CV_BLOCKS 2300
#define WT_BLOCKS 256
__global__ __launch_bounds__(256) void k_prelude(const float* __restrict__ reprs,
                                                 const float* __restrict__ word,
                                                 const float* __restrict__ wp1,
                                                 const float* __restrict__ Wb) {
    __shared__ float sh[64 * 65];
    int bx = blockIdx.x;
    if (bx < CV_BLOCKS) {
        size_t i = ((size_t)bx * 256 + threadIdx.x) * 8;
        const float* src; __nv_bfloat16* dst;
        if (i < N_REPRS) { src = reprs + i; dst = g_reprs_b + i; }
        else if (i < (size_t)N_REPRS + N_WORD) { size_t j = i - N_REPRS; src = word + j; dst = g_word_b + j; }
        else { size_t j = i - N_REPRS - N_WORD; src = wp1 + j; dst = g_Wp1b + j; }
        float4 a = *reinterpret_cast<const float4*>(src);
        float4 b = *reinterpret_cast<const float4*>(src + 4);
        uint4 o;
        o.x = pk2(a.x, a.y); o.y = pk2(a.z, a.w);
        o.z = pk2(b.x, b.y); o.w = pk2(b.z, b.w);
        *reinterpret_cast<uint4*>(dst) = o;
    } else if (bx < CV_BLOCKS + WT_BLOCKS) {
        int idx = bx - CV_BLOCKS;
        int n0 = (idx & 15) * 64, k0 = (idx >> 4) * 64;
        int r = threadIdx.x >> 2, cq = (threadIdx.x & 3) * 16;
        #pragma unroll
        for (int i = 0; i < 16; i++)
            sh[r * 65 + cq + i] = Wb[(size_t)(k0 + r) * 1025 + n0 + cq + i];
        __syncthreads();
        uint32_t pk[8];
        #pragma unroll
        for (int j = 0; j < 8; j++)
            pk[j] = pk2(sh[(cq + 2 * j) * 65 + r], sh[(cq + 2 * j + 1) * 65 + r]);
        __nv_bfloat16* dst = g_Wt + (size_t)(n0 + r) * 1024 + k0 + cq;
        *reinterpret_cast<uint4*>(dst)     = make_uint4(pk[0], pk[1], pk[2], pk[3]);
        *reinterpret_cast<uint4*>(dst + 8) = make_uint4(pk[4], pk[5], pk[6], pk[7]);
    } else if (bx < CV_BLOCKS + WT_BLOCKS + 64) {
        int idx = bx - CV_BLOCKS - WT_BLOCKS;
        float* wcol = sh;
        for (int i = threadIdx.x; i < 1024; i += 256) wcol[i] = Wb[(size_t)i * 1025 + 1024];
        __syncthreads();
        int wid = threadIdx.x >> 5, lane = threadIdx.x & 31;
        float wbias = Wb[(size_t)1024 * 1025 + 1024];
        #pragma unroll
        for (int rr = 0; rr < 4; rr++) {
            int row = idx * 32 + wid * 4 + rr;
            const float* ar = reprs + (size_t)row * 1024;
            float s = 0.f;
            for (int j = lane * 4; j < 1024; j += 128) {
                float4 a = *reinterpret_cast<const float4*>(ar + j);
                s += a.x * wcol[j] + a.y * wcol[j + 1] + a.z * wcol[j + 2] + a.w * wcol[j + 3];
            }
            #pragma unroll
            for (int o = 16; o; o >>= 1) s += __shfl_xor_sync(0xffffffff, s, o);
            if (lane == 0) g_Tbias[row] = s + wbias;
        }
    } else {
        int idx = (bx - CV_BLOCKS - WT_BLOCKS - 64) * 512 + threadIdx.x * 2;
        *reinterpret_cast<uint2*>(g_bitmap + idx) = make_uint2(0u, 0u);
    }
}

// set gold bits: atomicOr is idempotent == reference's .set(1.0)
__global__ __launch_bounds__(256) void k_setbits(const int* __restrict__ gold) {
    int g = blockIdx.x * 256 + threadIdx.x;
    int gb = gold[3 * g], gl = gold[3 * g + 1], gr = gold[3 * g + 2];
    int idx = (gb << 16) | (gl << 8) | gr;
    atomicOr(&g_bitmap[idx >> 5], 1u << (idx & 31));
}

// ===================== HMMA NT mainloop: S-stage, swizzled 64B rows =====================
template<int BM, int BN, int MI, int NI, int S>
__device__ __forceinline__ void mma_nt_loop(
    const __nv_bfloat16* __restrict__ Ag, int lda, int m0,
    const __nv_bfloat16* __restrict__ Bg, int ldb, int n0,
    int kbeg, int kend, float acc[MI][NI][4],
    __nv_bfloat16* As, __nv_bfloat16* Bs)   // [S][BM*32], [S][BN*32]
{
    constexpr int WC = BN / (8 * NI);
    int tid = threadIdx.x;
    int lane = tid & 31, warp = tid >> 5;
    int wm = warp / WC, wn = warp % WC;

    int ldr = tid >> 2, seg = tid & 3;
    int sw = seg ^ ((ldr >> 1) & 3);
    const __nv_bfloat16* Arow = Ag + (size_t)(m0 + ldr) * lda + seg * 8;
    const __nv_bfloat16* Brow = Bg + (size_t)(n0 + ldr) * ldb + seg * 8;
    uint32_t sa_st = sm_u32(As) + ldr * 64 + sw * 16;
    uint32_t sb_st = sm_u32(Bs) + ldr * 64 + sw * 16;
    constexpr int AIT = BM / 64, BIT = BN / 64;
    constexpr uint32_t stA = (uint32_t)BM * 64;
    constexpr uint32_t stB = (uint32_t)BN * 64;

    int a_r = lane & 15;
    uint32_t a_base = sm_u32(As) + (uint32_t)(wm * MI * 16 + a_r) * 64;
    int xa = (a_r >> 1) & 3;
    int a_hi = lane >> 4;
    int b_r = (lane & 7) + 8 * (lane >> 4);
    uint32_t b_base = sm_u32(Bs) + (uint32_t)(wn * NI * 8 + b_r) * 64;
    int xb = (b_r >> 1) & 3;
    int b_hi = (lane >> 3) & 1;

    int nc = (kend - kbeg) >> 5;
    #pragma unroll
    for (int p = 0; p < S; p++) {
        if (p < nc) {
            int kc = kbeg + p * 32;
            #pragma unroll
            for (int it = 0; it < AIT; it++)
                cp16(sa_st + p * stA + it * 4096, Arow + (size_t)it * 64 * lda + kc);
            #pragma unroll
            for (int it = 0; it < BIT; it++)
                cp16(sb_st + p * stB + it * 4096, Brow + (size_t)it * 64 * ldb + kc);
        }
        CP_COMMIT();
    }

    for (int c = 0; c < nc; c++) {
        asm volatile("cp.async.wait_group %0;\n" :: "n"(S - 1) : "memory");
        __syncthreads();
        int st = c % S;
        uint32_t a0 = a_base + st * stA;
        uint32_t b0 = b_base + st * stB;
        #pragma unroll
        for (int kk = 0; kk < 2; kk++) {
            uint32_t af[MI][4], bfr[NI][2];
            #pragma unroll
            for (int mi = 0; mi < MI; mi++)
                ldsm_x4(af[mi], a0 + mi * 1024 + ((((kk * 2 + a_hi)) ^ xa) << 4));
            #pragma unroll
            for (int nj = 0; nj < NI / 2; nj++) {
                uint32_t br[4];
                ldsm_x4(br, b0 + nj * 1024 + ((((kk * 2 + b_hi)) ^ xb) << 4));
                bfr[2 * nj][0] = br[0]; bfr[2 * nj][1] = br[1];
                bfr[2 * nj + 1][0] = br[2]; bfr[2 * nj + 1][1] = br[3];
            }
            #pragma unroll
            for (int mi = 0; mi < MI; mi++)
                #pragma unroll
                for (int ni = 0; ni < NI; ni++)
                    mma16816(acc[mi][ni], af[mi][0], af[mi][1], af[mi][2], af[mi][3],
                             bfr[ni][0], bfr[ni][1]);
        }
        __syncthreads();
        if (c + S < nc) {
            int kc = kbeg + (c + S) * 32;
            #pragma unroll
            for (int it = 0; it < AIT; it++)
                cp16(sa_st + st * stA + it * 4096, Arow + (size_t)it * 64 * lda + kc);
            #pragma unroll
            for (int it = 0; it < BIT; it++)
                cp16(sb_st + st * stB + it * 4096, Brow + (size_t)it * 64 * ldb + kc);
        }
        CP_COMMIT();
    }
}

#define NSTG 5
#define DYN_SMEM_128 (NSTG * (128 + 128) * 32 * 2)   // 80 KB

// ---- GEMM1: T_bf16 = reprs_b @ Wt^T (+ bias row), M=2048, N=1024, K=1024 ----
__global__ __launch_bounds__(256) void k_gemm1_mma(const float* __restrict__ Wb) {
    extern __shared__ __align__(16) __nv_bfloat16 dyn[];
    __nv_bfloat16* As = dyn;
    __nv_bfloat16* Bs = dyn + NSTG * 128 * 32;
    float acc[4][4][4] = {};
    int m0 = blockIdx.y * 128, n0 = blockIdx.x * 128;
    mma_nt_loop<128, 128, 4, 4, NSTG>(g_reprs_b, 1024, m0, g_Wt, 1024, n0, 0, 1024, acc, As, Bs);
    int lane = threadIdx.x & 31, warp = threadIdx.x >> 5;
    int wm = warp >> 2, wn = warp & 3, g = lane >> 2, tg = lane & 3;
    const float* brow = Wb + (size_t)1024 * 1025;
    #pragma unroll
    for (int mi = 0; mi < 4; mi++) {
        int m = m0 + wm * 64 + mi * 16 + g;
        #pragma unroll
        for (int ni = 0; ni < 4; ni++) {
            int n = n0 + wn * 32 + ni * 8 + 2 * tg;
            float b0 = brow[n], b1 = brow[n + 1];
            *reinterpret_cast<uint32_t*>(g_Tb + (size_t)m * 1024 + n) =
                pk2(acc[mi][ni][0] + b0, acc[mi][ni][1] + b1);
            *reinterpret_cast<uint32_t*>(g_Tb + (size_t)(m + 8) * 1024 + n) =
                pk2(acc[mi][ni][2] + b0, acc[mi][ni][3] + b1);
        }
    }
}

// ---- span GEMM 128x128 tiles + fused masked BCE epilogue ----
// grid (3, 8): t -> (x0,y0) in {(0,0),(0,128),(128,128)}, b = blockIdx.y
__global__ __launch_bounds__(256) void k_span_mma(const int* __restrict__ seq_len) {
    extern __shared__ __align__(16) __nv_bfloat16 dyn[];
    __nv_bfloat16* As = dyn;
    __nv_bfloat16* Bs = dyn + NSTG * 128 * 32;
    __shared__ float red[256];
    int t = blockIdx.x, b = blockIdx.y;
    int x0 = (t == 2) ? 128 : 0;
    int y0 = (t == 0) ? 0 : 128;
    int slot = b * 3 + t;
    int sl = seq_len[b];
    int tid = threadIdx.x;
    if (y0 > sl) {
        if (tid == 0) { g_span_sum[slot] = 0.f; g_span_cnt2[slot] = 0.f; }
        return;
    }
    float acc[4][4][4] = {};
    mma_nt_loop<128, 128, 4, 4, NSTG>(g_Tb + (size_t)b * Ln * Dn, 1024, x0,
                                      g_reprs_b + (size_t)b * Ln * Dn, 1024, y0, 0, 1024, acc, As, Bs);
    int lane = tid & 31, warp = tid >> 5;
    int wm = warp >> 2, wn = warp & 3, g = lane >> 2, tg = lane & 3;
    float lsum = 0.f, lcnt = 0.f;
    #pragma unroll
    for (int mi = 0; mi < 4; mi++) {
        int xA = x0 + wm * 64 + mi * 16 + g;
        int xB = xA + 8;
        float tbA = g_Tbias[b * Ln + xA];
        float tbB = g_Tbias[b * Ln + xB];
        #pragma unroll
        for (int ni = 0; ni < 4; ni++) {
            int y = y0 + wn * 32 + ni * 8 + 2 * tg;
            #pragma unroll
            for (int e = 0; e < 4; e++) {
                int yy = y + (e & 1);
                int xx = (e < 2) ? xA : xB;
                float tb = (e < 2) ? tbA : tbB;
                if (yy > xx && yy <= sl) {
                    float s = acc[mi][ni][e] + tb;
                    lsum += fmaxf(s, 0.f) + log1pf(expf(-fabsf(s)));
                    int idx = (b << 16) | (xx << 8) | yy;
                    if ((g_bitmap[idx >> 5] >> (idx & 31)) & 1u) lsum -= s;
                    lcnt += 1.f;
                }
            }
        }
    }
    red[tid] = lsum; __syncthreads();
    for (int s = 128; s > 0; s >>= 1) { if (tid < s) red[tid] += red[tid + s]; __syncthreads(); }
    float tot = red[0]; __syncthreads();
    red[tid] = lcnt; __syncthreads();
    for (int s = 128; s > 0; s >>= 1) { if (tid < s) red[tid] += red[tid + s]; __syncthreads(); }
    if (tid == 0) { g_span_sum[slot] = tot; g_span_cnt2[slot] = red[0]; }
}

// ---- h1 split-K=8: partials[ks] = gold_b @ Wp1_b^T over K slice ----
__global__ __launch_bounds__(256) void k_h1_mma() {
    extern __shared__ __align__(16) __nv_bfloat16 dyn[];
    __nv_bfloat16* As = dyn;
    __nv_bfloat16* Bs = dyn + NSTG * 128 * 32;
    float acc[4][4][4] = {};
    int n0 = blockIdx.x * 128, m0 = blockIdx.y * 128, ks = blockIdx.z;
    mma_nt_loop<128, 128, 4, 4, NSTG>(g_goldb, 2048, m0, g_Wp1b, 2048, n0,
                                      ks * 256, ks * 256 + 256, acc, As, Bs);
    int lane = threadIdx.x & 31, warp = threadIdx.x >> 5;
    int wm = warp >> 2, wn = warp & 3, g = lane >> 2, tg = lane & 3;
    float* dst = g_h1p + (size_t)ks * 512 * 256;
    #pragma unroll
    for (int mi = 0; mi < 4; mi++) {
        int m = m0 + wm * 64 + mi * 16 + g;
        #pragma unroll
        for (int ni = 0; ni < 4; ni++) {
            int n = n0 + wn * 32 + ni * 8 + 2 * tg;
            *reinterpret_cast<float2*>(dst + (size_t)m * 256 + n) =
                make_float2(acc[mi][ni][0], acc[mi][ni][1]);
            *reinterpret_cast<float2*>(dst + (size_t)(m + 8) * 256 + n) =
                make_float2(acc[mi][ni][2], acc[mi][ni][3]);
        }
    }
}

// ===================== non-tensor kernels =====================

// gold_repr (bf16) = concat(end-start, maxpool word_repr[start:end))
__global__ __launch_bounds__(256) void k_gold_repr(const float* __restrict__ reprs,
                                                   const int* __restrict__ span_start,
                                                   const int* __restrict__ span_end) {
    int row = blockIdx.x, tid = threadIdx.x;
    int b = row >> 6;
    int s = span_start[row], e = span_end[row];
    const float4* rs = reinterpret_cast<const float4*>(reprs + ((size_t)b * Ln + s) * Dn);
    const float4* re = reinterpret_cast<const float4*>(reprs + ((size_t)b * Ln + e) * Dn);
    float4 a = re[tid], c = rs[tid];
    uint2 o;
    o.x = pk2(a.x - c.x, a.y - c.y);
    o.y = pk2(a.z - c.z, a.w - c.w);
    *reinterpret_cast<uint2*>(g_goldb + (size_t)row * 2048 + tid * 4) = o;

    float m0 = NEGV, m1 = NEGV, m2 = NEGV, m3 = NEGV;
    float n0 = NEGV, n1 = NEGV, n2 = NEGV, n3 = NEGV;
    const __nv_bfloat16* wb = g_word_b + (size_t)b * Wn * Dn + tid * 4;
    int ee = min(e, Wn);
    int w = s;
    for (; w + 1 < ee; w += 2) {
        uint2 v0 = *reinterpret_cast<const uint2*>(wb + (size_t)w * Dn);
        uint2 v1 = *reinterpret_cast<const uint2*>(wb + (size_t)(w + 1) * Dn);
        float2 a0 = upk2(v0.x), a1 = upk2(v0.y);
        float2 b0 = upk2(v1.x), b1 = upk2(v1.y);
        m0 = fmaxf(m0, a0.x); m1 = fmaxf(m1, a0.y);
        m2 = fmaxf(m2, a1.x); m3 = fmaxf(m3, a1.y);
        n0 = fmaxf(n0, b0.x); n1 = fmaxf(n1, b0.y);
        n2 = fmaxf(n2, b1.x); n3 = fmaxf(n3, b1.y);
    }
    if (w < ee) {
        uint2 v0 = *reinterpret_cast<const uint2*>(wb + (size_t)w * Dn);
        float2 a0 = upk2(v0.x), a1 = upk2(v0.y);
        m0 = fmaxf(m0, a0.x); m1 = fmaxf(m1, a0.y);
        m2 = fmaxf(m2, a1.x); m3 = fmaxf(m3, a1.y);
    }
    m0 = fmaxf(m0, n0); m1 = fmaxf(m1, n1); m2 = fmaxf(m2, n2); m3 = fmaxf(m3, n3);
    uint2 p; p.x = pk2(m0, m1); p.y = pk2(m2, m3);
    *reinterpret_cast<uint2*>(g_goldb + (size_t)row * 2048 + 1024 + tid * 4) = p;
}

// fused tail: LN(relu) + h2 = h@Wp2^T+b2 + logits = h2@Lab^T + log-softmax CE
__global__ __launch_bounds__(256) void k_tail(const float* __restrict__ bp1,
                                              const float* __restrict__ gamma,
                                              const float* __restrict__ beta,
                                              const float* __restrict__ Wp2,
                                              const float* __restrict__ bp2,
                                              const float* __restrict__ lab,
                                              const int* __restrict__ chart,
                                              const int* __restrict__ action_len) {
    __shared__ float h[8][256];
    __shared__ float h2[8][256];
    __shared__ float lg[8][128];
    __shared__ float red[128];
    int tid = threadIdx.x;
    int r0 = blockIdx.x * 8;
    int warp = tid >> 5, lane = tid & 31;

    {
        int row = r0 + warp;
        int c0 = lane * 8;
        float x[8];
        #pragma unroll
        for (int j = 0; j < 8; j++) x[j] = bp1[c0 + j];
        #pragma unroll
        for (int p = 0; p < 8; p++) {
            const float* src = g_h1p + ((size_t)p * 512 + row) * 256 + c0;
            float4 v0 = *reinterpret_cast<const float4*>(src);
            float4 v1 = *reinterpret_cast<const float4*>(src + 4);
            x[0] += v0.x; x[1] += v0.y; x[2] += v0.z; x[3] += v0.w;
            x[4] += v1.x; x[5] += v1.y; x[6] += v1.z; x[7] += v1.w;
        }
        float sum = 0.f;
        #pragma unroll
        for (int j = 0; j < 8; j++) sum += x[j];
        #pragma unroll
        for (int o = 16; o; o >>= 1) sum += __shfl_xor_sync(0xffffffff, sum, o);
        float mean = sum * (1.0f / En);
        float s2 = 0.f;
        #pragma unroll
        for (int j = 0; j < 8; j++) { x[j] -= mean; s2 += x[j] * x[j]; }
        #pragma unroll
        for (int o = 16; o; o >>= 1) s2 += __shfl_xor_sync(0xffffffff, s2, o);
        float inv = rsqrtf(s2 * (1.0f / En) + 1e-5f);
        #pragma unroll
        for (int j = 0; j < 8; j++) {
            float y = x[j] * inv * gamma[c0 + j] + beta[c0 + j];
            h[warp][c0 + j] = fmaxf(y, 0.f);
        }
    }
    __syncthreads();
    {
        float acc[8] = {0, 0, 0, 0, 0, 0, 0, 0};
        const float4* wr = reinterpret_cast<const float4*>(Wp2 + (size_t)tid * 256);
        for (int k = 0; k < 64; k++) {
            float4 w = wr[k];
            #pragma unroll
            for (int r = 0; r < 8; r++)
                acc[r] += w.x * h[r][4 * k] + w.y * h[r][4 * k + 1]
                        + w.z * h[r][4 * k + 2] + w.w * h[r][4 * k + 3];
        }
        float bb = bp2[tid];
        #pragma unroll
        for (int r = 0; r < 8; r++) h2[r][tid] = acc[r] + bb;
    }
    __syncthreads();
    if (tid < 128) {
        float acc[8] = {0, 0, 0, 0, 0, 0, 0, 0};
        const float4* lr = reinterpret_cast<const float4*>(lab + (size_t)tid * 256);
        for (int k = 0; k < 64; k++) {
            float4 w = lr[k];
            #pragma unroll
            for (int r = 0; r < 8; r++)
                acc[r] += w.x * h2[r][4 * k] + w.y * h2[r][4 * k + 1]
                        + w.z * h2[r][4 * k + 2] + w.w * h2[r][4 * k + 3];
        }
        #pragma unroll
        for (int r = 0; r < 8; r++) lg[r][tid] = acc[r];
    }
    __syncthreads();
    for (int r = 0; r < 8; r++) {
        if (tid < 128) red[tid] = lg[r][tid];
        __syncthreads();
        for (int s = 64; s > 0; s >>= 1) { if (tid < s) red[tid] = fmaxf(red[tid], red[tid + s]); __syncthreads(); }
        float mx = red[0]; __syncthreads();
        if (tid < 128) red[tid] = expf(lg[r][tid] - mx);
        __syncthreads();
        for (int s = 64; s > 0; s >>= 1) { if (tid < s) red[tid] += red[tid + s]; __syncthreads(); }
        if (tid == 0) {
            int row = r0 + r;
            int b = row >> 6, a = row & 63;
            float lse = logf(red[0]);
            float ce = -(lg[r][chart[row]] - mx - lse);
            g_ce_part[row] = (a < action_len[b]) ? ce : 0.f;
        }
        __syncthreads();
    }
}

// final deterministic reduction
__global__ __launch_bounds__(512) void k_final(const int* __restrict__ action_len,
                                               float* __restrict__ out) {
    __shared__ float red[512];
    int tid = threadIdx.x;
    red[tid] = (tid < 24 ? g_span_sum[tid] : 0.f); __syncthreads();
    for (int s = 256; s > 0; s >>= 1) { if (tid < s) red[tid] += red[tid + s]; __syncthreads(); }
    float span_num = red[0]; __syncthreads();

    red[tid] = (tid < 24 ? g_span_cnt2[tid] : 0.f); __syncthreads();
    for (int s = 256; s > 0; s >>= 1) { if (tid < s) red[tid] += red[tid + s]; __syncthreads(); }
    float span_cnt = red[0]; __syncthreads();

    red[tid] = g_ce_part[tid]; __syncthreads();
    for (int s = 256; s > 0; s >>= 1) { if (tid < s) red[tid] += red[tid + s]; __syncthreads(); }
    float ce_sum = red[0];

    if (tid == 0) {
        int lc = 0;
        for (int b = 0; b < Bn; b++) lc += action_len[b];
        out[0] = span_num / span_cnt + ce_sum / (float)lc;
    }
}

// ===================== launch =====================
extern "C" void kernel_launch(void* const* d_in, const int* in_sizes, int n_in,
                              void* d_out, int out_size) {
    const float* reprs      = (const float*)d_in[0];
    const float* word_repr  = (const float*)d_in[1];
    const int*   seq_len    = (const int*)d_in[2];
    const int*   gold_span  = (const int*)d_in[3];
    const int*   span_start = (const int*)d_in[4];
    const int*   span_end   = (const int*)d_in[5];
    const int*   chart      = (const int*)d_in[6];
    const int*   action_len = (const int*)d_in[7];
    const float* Wb         = (const float*)d_in[8];
    const float* Wp1        = (const float*)d_in[9];
    const float* bp1        = (const float*)d_in[10];
    const float* gamma      = (const float*)d_in[11];
    const float* beta       = (const float*)d_in[12];
    const float* Wp2        = (const float*)d_in[13];
    const float* bp2        = (const float*)d_in[14];
    const float* lab        = (const float*)d_in[15];
    float* out = (float*)d_out;

    static bool attr_done = false;
    if (!attr_done) {
        cudaFuncSetAttribute(k_gemm1_mma, cudaFuncAttributeMaxDynamicSharedMemorySize, DYN_SMEM_128);
        cudaFuncSetAttribute(k_span_mma,  cudaFuncAttributeMaxDynamicSharedMemorySize, DYN_SMEM_128);
        cudaFuncSetAttribute(k_h1_mma,    cudaFuncAttributeMaxDynamicSharedMemorySize, DYN_SMEM_128);
        attr_done = true;
    }

    // prelude: conversions + W^T + bias column + bitmap zero; then gold bits
    k_prelude<<<CV_BLOCKS + WT_BLOCKS + 64 + 8, 256>>>(reprs, word_repr, Wp1, Wb);
    k_setbits<<<8, 256>>>(gold_span);

    // tensor-core (HMMA) GEMMs, 5-stage pipelines
    k_gemm1_mma<<<dim3(8, 16), 256, DYN_SMEM_128>>>(Wb);
    k_span_mma<<<dim3(3, 8), 256, DYN_SMEM_128>>>(seq_len);

    // label path
    k_gold_repr<<<Bn * An, 256>>>(reprs, span_start, span_end);
    k_h1_mma<<<dim3(2, 4, 8), 256, DYN_SMEM_128>>>();
    k_tail<<<64, 256>>>(bp1, gamma, beta, Wp2, bp2, lab, chart, action_len);

    k_final<<<1, 512>>>(action_len, out);
}

// round 13
// speedup vs baseline: 1.2588x; 1.2588x over previous
// R13: revert span to 64x64/80-block (R12's 128x128 cut SMs 80->24 and doubled MACs on the
// ~500 MAC/cyc/SM legacy-HMMA ceiling). NEW: merge independent kernels into 2 stages
// (gemm1||gold_repr||setbits; span||h1) -> 5 launches, full-chip waves.
#include <cuda_runtime.h>
#include <cuda_bf16.h>
#include <math.h>
#include <stdint.h>

// Problem constants
#define Bn   8
#define Ln   256
#define Dn   1024
#define An   64
#define Vn   128
#define En   256
#define Gn   2048
#define Wn   255
#define NEGV (-1000.0f)

// bf16 pack/unpack
__device__ __forceinline__ uint32_t pk2(float a, float b) {
    __nv_bfloat162 h; h.x = __float2bfloat16(a); h.y = __float2bfloat16(b);
    return *reinterpret_cast<uint32_t*>(&h);
}
__device__ __forceinline__ float2 upk2(uint32_t u) {
    __nv_bfloat162 h = *reinterpret_cast<__nv_bfloat162*>(&u);
    return __bfloat1622float2(h);
}
__device__ __forceinline__ uint32_t sm_u32(const void* p) {
    uint32_t a;
    asm("{ .reg .u64 t; cvta.to.shared.u64 t, %1; cvt.u32.u64 %0, t; }" : "=r"(a) : "l"(p));
    return a;
}

// warp mma: D(16x8,f32) += A(16x16,bf16,row) * B(16x8,bf16,col)
__device__ __forceinline__ void mma16816(float d[4], uint32_t a0, uint32_t a1,
                                         uint32_t a2, uint32_t a3,
                                         uint32_t b0, uint32_t b1) {
    asm volatile(
        "mma.sync.aligned.m16n8k16.row.col.f32.bf16.bf16.f32 "
        "{%0,%1,%2,%3}, {%4,%5,%6,%7}, {%8,%9}, {%0,%1,%2,%3};\n"
        : "+f"(d[0]), "+f"(d[1]), "+f"(d[2]), "+f"(d[3])
        : "r"(a0), "r"(a1), "r"(a2), "r"(a3), "r"(b0), "r"(b1));
}
__device__ __forceinline__ void ldsm_x4(uint32_t r[4], uint32_t addr) {
    asm volatile("ldmatrix.sync.aligned.m8n8.x4.shared.b16 {%0,%1,%2,%3}, [%4];\n"
                 : "=r"(r[0]), "=r"(r[1]), "=r"(r[2]), "=r"(r[3]) : "r"(addr));
}
__device__ __forceinline__ void cp16(uint32_t s_dst, const void* g_src) {
    asm volatile("cp.async.cg.shared.global [%0], [%1], 16;\n" :: "r"(s_dst), "l"(g_src));
}
#define CP_COMMIT() asm volatile("cp.async.commit_group;\n" ::: "memory")

// ===================== device scratch =====================
__device__ __align__(16) __nv_bfloat16 g_reprs_b[Bn * Ln * Dn];   // 4 MB
__device__ __align__(16) __nv_bfloat16 g_word_b[Bn * Wn * Dn];    // ~4 MB
__device__ __align__(16) __nv_bfloat16 g_Wp1b[En * 2 * Dn];       // 1 MB
__device__ __align__(16) __nv_bfloat16 g_Wt[Dn * Dn];             // W^T bf16, 2 MB
__device__ __align__(16) __nv_bfloat16 g_Tb[Bn * Ln * Dn];        // T bf16, 4 MB
__device__ float g_Tbias[Bn * Ln];                                 // T[:,1024] fp32
__device__ __align__(16) __nv_bfloat16 g_goldb[Bn * An * 2 * Dn]; // 2 MB
__device__ float g_h1p[8 * 512 * 256];                             // h1 split-K partials
__device__ __align__(16) uint32_t g_bitmap[Bn * Ln * Ln / 32];     // gold bitmap, 64 KB
__device__ float g_span_sum[80];
__device__ float g_span_cnt2[80];
__device__ float g_ce_part[512];

// ===================== merged prelude =====================
#define N_REPRS (Bn * Ln * Dn)        // 2097152
#define N_WORD  (Bn * Wn * Dn)        // 2088960
#define N_WP1   (En * 2 * Dn)         // 524288
#define CV_BLOCKS 2300
#define WT_BLOCKS 256
__global__ __launch_bounds__(256) void k_prelude(const float* __restrict__ reprs,
                                                 const float* __restrict__ word,
                                                 const float* __restrict__ wp1,
                                                 const float* __restrict__ Wb) {
    __shared__ float sh[64 * 65];
    int bx = blockIdx.x;
    if (bx < CV_BLOCKS) {
        size_t i = ((size_t)bx * 256 + threadIdx.x) * 8;
        const float* src; __nv_bfloat16* dst;
        if (i < N_REPRS) { src = reprs + i; dst = g_reprs_b + i; }
        else if (i < (size_t)N_REPRS + N_WORD) { size_t j = i - N_REPRS; src = word + j; dst = g_word_b + j; }
        else { size_t j = i - N_REPRS - N_WORD; src = wp1 + j; dst = g_Wp1b + j; }
        float4 a = *reinterpret_cast<const float4*>(src);
        float4 b = *reinterpret_cast<const float4*>(src + 4);
        uint4 o;
        o.x = pk2(a.x, a.y); o.y = pk2(a.z, a.w);
        o.z = pk2(b.x, b.y); o.w = pk2(b.z, b.w);
        *reinterpret_cast<uint4*>(dst) = o;
    } else if (bx < CV_BLOCKS + WT_BLOCKS) {
        int idx = bx - CV_BLOCKS;
        int n0 = (idx & 15) * 64, k0 = (idx >> 4) * 64;
        int r = threadIdx.x >> 2, cq = (threadIdx.x & 3) * 16;
        #pragma unroll
        for (int i = 0; i < 16; i++)
            sh[r * 65 + cq + i] = Wb[(size_t)(k0 + r) * 1025 + n0 + cq + i];
        __syncthreads();
        uint32_t pk[8];
        #pragma unroll
        for (int j = 0; j < 8; j++)
            pk[j] = pk2(sh[(cq + 2 * j) * 65 + r], sh[(cq + 2 * j + 1) * 65 + r]);
        __nv_bfloat16* dst = g_Wt + (size_t)(n0 + r) * 1024 + k0 + cq;
        *reinterpret_cast<uint4*>(dst)     = make_uint4(pk[0], pk[1], pk[2], pk[3]);
        *reinterpret_cast<uint4*>(dst + 8) = make_uint4(pk[4], pk[5], pk[6], pk[7]);
    } else if (bx < CV_BLOCKS + WT_BLOCKS + 64) {
        int idx = bx - CV_BLOCKS - WT_BLOCKS;
        float* wcol = sh;
        for (int i = threadIdx.x; i < 1024; i += 256) wcol[i] = Wb[(size_t)i * 1025 + 1024];
        __syncthreads();
        int wid = threadIdx.x >> 5, lane = threadIdx.x & 31;
        float wbias = Wb[(size_t)1024 * 1025 + 1024];
        #pragma unroll
        for (int rr = 0; rr < 4; rr++) {
            int row = idx * 32 + wid * 4 + rr;
            const float* ar = reprs + (size_t)row * 1024;
            float s = 0.f;
            for (int j = lane * 4; j < 1024; j += 128) {
                float4 a = *reinterpret_cast<const float4*>(ar + j);
                s += a.x * wcol[j] + a.y * wcol[j + 1] + a.z * wcol[j + 2] + a.w * wcol[j + 3];
            }
            #pragma unroll
            for (int o = 16; o; o >>= 1) s += __shfl_xor_sync(0xffffffff, s, o);
            if (lane == 0) g_Tbias[row] = s + wbias;
        }
    } else {
        int idx = (bx - CV_BLOCKS - WT_BLOCKS - 64) * 512 + threadIdx.x * 2;
        *reinterpret_cast<uint2*>(g_bitmap + idx) = make_uint2(0u, 0u);
    }
}

// ===================== HMMA NT mainloop: S-stage, swizzled 64B rows =====================
template<int BM, int BN, int MI, int NI, int S>
__device__ __forceinline__ void mma_nt_loop(
    const __nv_bfloat16* __restrict__ Ag, int lda, int m0,
    const __nv_bfloat16* __restrict__ Bg, int ldb, int n0,
    int kbeg, int kend, float acc[MI][NI][4],
    __nv_bfloat16* As, __nv_bfloat16* Bs)   // [S][BM*32], [S][BN*32]
{
    constexpr int WC = BN / (8 * NI);
    int tid = threadIdx.x;
    int lane = tid & 31, warp = tid >> 5;
    int wm = warp / WC, wn = warp % WC;

    int ldr = tid >> 2, seg = tid & 3;
    int sw = seg ^ ((ldr >> 1) & 3);
    const __nv_bfloat16* Arow = Ag + (size_t)(m0 + ldr) * lda + seg * 8;
    const __nv_bfloat16* Brow = Bg + (size_t)(n0 + ldr) * ldb + seg * 8;
    uint32_t sa_st = sm_u32(As) + ldr * 64 + sw * 16;
    uint32_t sb_st = sm_u32(Bs) + ldr * 64 + sw * 16;
    constexpr int AIT = BM / 64, BIT = BN / 64;
    constexpr uint32_t stA = (uint32_t)BM * 64;
    constexpr uint32_t stB = (uint32_t)BN * 64;

    int a_r = lane & 15;
    uint32_t a_base = sm_u32(As) + (uint32_t)(wm * MI * 16 + a_r) * 64;
    int xa = (a_r >> 1) & 3;
    int a_hi = lane >> 4;
    int b_r = (lane & 7) + 8 * (lane >> 4);
    uint32_t b_base = sm_u32(Bs) + (uint32_t)(wn * NI * 8 + b_r) * 64;
    int xb = (b_r >> 1) & 3;
    int b_hi = (lane >> 3) & 1;

    int nc = (kend - kbeg) >> 5;
    #pragma unroll
    for (int p = 0; p < S; p++) {
        if (p < nc) {
            int kc = kbeg + p * 32;
            #pragma unroll
            for (int it = 0; it < AIT; it++)
                cp16(sa_st + p * stA + it * 4096, Arow + (size_t)it * 64 * lda + kc);
            #pragma unroll
            for (int it = 0; it < BIT; it++)
                cp16(sb_st + p * stB + it * 4096, Brow + (size_t)it * 64 * ldb + kc);
        }
        CP_COMMIT();
    }

    for (int c = 0; c < nc; c++) {
        asm volatile("cp.async.wait_group %0;\n" :: "n"(S - 1) : "memory");
        __syncthreads();
        int st = c % S;
        uint32_t a0 = a_base + st * stA;
        uint32_t b0 = b_base + st * stB;
        #pragma unroll
        for (int kk = 0; kk < 2; kk++) {
            uint32_t af[MI][4], bfr[NI][2];
            #pragma unroll
            for (int mi = 0; mi < MI; mi++)
                ldsm_x4(af[mi], a0 + mi * 1024 + ((((kk * 2 + a_hi)) ^ xa) << 4));
            #pragma unroll
            for (int nj = 0; nj < NI / 2; nj++) {
                uint32_t br[4];
                ldsm_x4(br, b0 + nj * 1024 + ((((kk * 2 + b_hi)) ^ xb) << 4));
                bfr[2 * nj][0] = br[0]; bfr[2 * nj][1] = br[1];
                bfr[2 * nj + 1][0] = br[2]; bfr[2 * nj + 1][1] = br[3];
            }
            #pragma unroll
            for (int mi = 0; mi < MI; mi++)
                #pragma unroll
                for (int ni = 0; ni < NI; ni++)
                    mma16816(acc[mi][ni], af[mi][0], af[mi][1], af[mi][2], af[mi][3],
                             bfr[ni][0], bfr[ni][1]);
        }
        __syncthreads();
        if (c + S < nc) {
            int kc = kbeg + (c + S) * 32;
            #pragma unroll
            for (int it = 0; it < AIT; it++)
                cp16(sa_st + st * stA + it * 4096, Arow + (size_t)it * 64 * lda + kc);
            #pragma unroll
            for (int it = 0; it < BIT; it++)
                cp16(sb_st + st * stB + it * 4096, Brow + (size_t)it * 64 * ldb + kc);
        }
        CP_COMMIT();
    }
}

#define NSTG 5
#define DYN_SMEM_128 (NSTG * (128 + 128) * 32 * 2)   // 80 KB

// ---- stage1 sub-bodies ----
__device__ void gemm1_body(const float* __restrict__ Wb, int m_t, int n_t,
                           __nv_bfloat16* As, __nv_bfloat16* Bs) {
    float acc[4][4][4] = {};
    int m0 = m_t * 128, n0 = n_t * 128;
    mma_nt_loop<128, 128, 4, 4, NSTG>(g_reprs_b, 1024, m0, g_Wt, 1024, n0, 0, 1024, acc, As, Bs);
    int lane = threadIdx.x & 31, warp = threadIdx.x >> 5;
    int wm = warp >> 2, wn = warp & 3, g = lane >> 2, tg = lane & 3;
    const float* brow = Wb + (size_t)1024 * 1025;
    #pragma unroll
    for (int mi = 0; mi < 4; mi++) {
        int m = m0 + wm * 64 + mi * 16 + g;
        #pragma unroll
        for (int ni = 0; ni < 4; ni++) {
            int n = n0 + wn * 32 + ni * 8 + 2 * tg;
            float b0 = brow[n], b1 = brow[n + 1];
            *reinterpret_cast<uint32_t*>(g_Tb + (size_t)m * 1024 + n) =
                pk2(acc[mi][ni][0] + b0, acc[mi][ni][1] + b1);
            *reinterpret_cast<uint32_t*>(g_Tb + (size_t)(m + 8) * 1024 + n) =
                pk2(acc[mi][ni][2] + b0, acc[mi][ni][3] + b1);
        }
    }
}

__device__ void gold_repr_body(const float* __restrict__ reprs,
                               const int* __restrict__ span_start,
                               const int* __restrict__ span_end, int row) {
    int tid = threadIdx.x;
    int b = row >> 6;
    int s = span_start[row], e = span_end[row];
    const float4* rs = reinterpret_cast<const float4*>(reprs + ((size_t)b * Ln + s) * Dn);
    const float4* re = reinterpret_cast<const float4*>(reprs + ((size_t)b * Ln + e) * Dn);
    float4 a = re[tid], c = rs[tid];
    uint2 o;
    o.x = pk2(a.x - c.x, a.y - c.y);
    o.y = pk2(a.z - c.z, a.w - c.w);
    *reinterpret_cast<uint2*>(g_goldb + (size_t)row * 2048 + tid * 4) = o;

    float m0 = NEGV, m1 = NEGV, m2 = NEGV, m3 = NEGV;
    float n0 = NEGV, n1 = NEGV, n2 = NEGV, n3 = NEGV;
    const __nv_bfloat16* wb = g_word_b + (size_t)b * Wn * Dn + tid * 4;
    int ee = min(e, Wn);
    int w = s;
    for (; w + 1 < ee; w += 2) {
        uint2 v0 = *reinterpret_cast<const uint2*>(wb + (size_t)w * Dn);
        uint2 v1 = *reinterpret_cast<const uint2*>(wb + (size_t)(w + 1) * Dn);
        float2 a0 = upk2(v0.x), a1 = upk2(v0.y);
        float2 b0 = upk2(v1.x), b1 = upk2(v1.y);
        m0 = fmaxf(m0, a0.x); m1 = fmaxf(m1, a0.y);
        m2 = fmaxf(m2, a1.x); m3 = fmaxf(m3, a1.y);
        n0 = fmaxf(n0, b0.x); n1 = fmaxf(n1, b0.y);
        n2 = fmaxf(n2, b1.x); n3 = fmaxf(n3, b1.y);
    }
    if (w < ee) {
        uint2 v0 = *reinterpret_cast<const uint2*>(wb + (size_t)w * Dn);
        float2 a0 = upk2(v0.x), a1 = upk2(v0.y);
        m0 = fmaxf(m0, a0.x); m1 = fmaxf(m1, a0.y);
        m2 = fmaxf(m2, a1.x); m3 = fmaxf(m3, a1.y);
    }
    m0 = fmaxf(m0, n0); m1 = fmaxf(m1, n1); m2 = fmaxf(m2, n2); m3 = fmaxf(m3, n3);
    uint2 p; p.x = pk2(m0, m1); p.y = pk2(m2, m3);
    *reinterpret_cast<uint2*>(g_goldb + (size_t)row * 2048 + 1024 + tid * 4) = p;
}

// ---- stage1: gemm1 (128) | gold_repr (512) | setbits (8) ----
__global__ __launch_bounds__(256) void k_stage1(const float* __restrict__ Wb,
                                                const float* __restrict__ reprs,
                                                const int* __restrict__ span_start,
                                                const int* __restrict__ span_end,
                                                const int* __restrict__ gold) {
    extern __shared__ __align__(16) __nv_bfloat16 dyn[];
    int bx = blockIdx.x;
    if (bx < 128) {
        gemm1_body(Wb, bx >> 3, bx & 7, dyn, dyn + NSTG * 128 * 32);
    } else if (bx < 640) {
        gold_repr_body(reprs, span_start, span_end, bx - 128);
    } else {
        int g = (bx - 640) * 256 + threadIdx.x;
        int gb = gold[3 * g], gl = gold[3 * g + 1], gr = gold[3 * g + 2];
        int idx = (gb << 16) | (gl << 8) | gr;
        atomicOr(&g_bitmap[idx >> 5], 1u << (idx & 31));
    }
}

// ---- stage2 sub-bodies ----
__constant__ int c_xt[10] = {0, 0, 0, 0, 1, 1, 1, 2, 2, 3};
__constant__ int c_yt[10] = {0, 1, 2, 3, 1, 2, 3, 2, 3, 3};

__device__ void span_body(const int* __restrict__ seq_len, int t, int b,
                          __nv_bfloat16* As, __nv_bfloat16* Bs, float* red) {
    int x0 = c_xt[t] * 64, y0 = c_yt[t] * 64;
    int slot = b * 10 + t;
    int sl = seq_len[b];
    int tid = threadIdx.x;
    if (y0 > sl) {
        if (tid == 0) { g_span_sum[slot] = 0.f; g_span_cnt2[slot] = 0.f; }
        return;
    }
    float acc[2][2][4] = {};
    mma_nt_loop<64, 64, 2, 2, NSTG>(g_Tb + (size_t)b * Ln * Dn, 1024, x0,
                                    g_reprs_b + (size_t)b * Ln * Dn, 1024, y0, 0, 1024, acc, As, Bs);
    int lane = tid & 31, warp = tid >> 5;
    int wm = warp >> 2, wn = warp & 3, g = lane >> 2, tg = lane & 3;
    float lsum = 0.f, lcnt = 0.f;
    #pragma unroll
    for (int mi = 0; mi < 2; mi++) {
        int xA = x0 + wm * 32 + mi * 16 + g;
        int xB = xA + 8;
        float tbA = g_Tbias[b * Ln + xA];
        float tbB = g_Tbias[b * Ln + xB];
        #pragma unroll
        for (int ni = 0; ni < 2; ni++) {
            int y = y0 + wn * 16 + ni * 8 + 2 * tg;
            #pragma unroll
            for (int e = 0; e < 4; e++) {
                int yy = y + (e & 1);
                int xx = (e < 2) ? xA : xB;
                float tb = (e < 2) ? tbA : tbB;
                if (yy > xx && yy <= sl) {
                    float s = acc[mi][ni][e] + tb;
                    lsum += fmaxf(s, 0.f) + log1pf(expf(-fabsf(s)));
                    int idx = (b << 16) | (xx << 8) | yy;
                    if ((g_bitmap[idx >> 5] >> (idx & 31)) & 1u) lsum -= s;
                    lcnt += 1.f;
                }
            }
        }
    }
    red[tid] = lsum; __syncthreads();
    for (int s = 128; s > 0; s >>= 1) { if (tid < s) red[tid] += red[tid + s]; __syncthreads(); }
    float tot = red[0]; __syncthreads();
    red[tid] = lcnt; __syncthreads();
    for (int s = 128; s > 0; s >>= 1) { if (tid < s) red[tid] += red[tid + s]; __syncthreads(); }
    if (tid == 0) { g_span_sum[slot] = tot; g_span_cnt2[slot] = red[0]; }
}

__device__ void h1_body(int n_t, int m_t, int ks, __nv_bfloat16* As, __nv_bfloat16* Bs) {
    float acc[4][4][4] = {};
    int n0 = n_t * 128, m0 = m_t * 128;
    mma_nt_loop<128, 128, 4, 4, NSTG>(g_goldb, 2048, m0, g_Wp1b, 2048, n0,
                                      ks * 256, ks * 256 + 256, acc, As, Bs);
    int lane = threadIdx.x & 31, warp = threadIdx.x >> 5;
    int wm = warp >> 2, wn = warp & 3, g = lane >> 2, tg = lane & 3;
    float* dst = g_h1p + (size_t)ks * 512 * 256;
    #pragma unroll
    for (int mi = 0; mi < 4; mi++) {
        int m = m0 + wm * 64 + mi * 16 + g;
        #pragma unroll
        for (int ni = 0; ni < 4; ni++) {
            int n = n0 + wn * 32 + ni * 8 + 2 * tg;
            *reinterpret_cast<float2*>(dst + (size_t)m * 256 + n) =
                make_float2(acc[mi][ni][0], acc[mi][ni][1]);
            *reinterpret_cast<float2*>(dst + (size_t)(m + 8) * 256 + n) =
                make_float2(acc[mi][ni][2], acc[mi][ni][3]);
        }
    }
}

// ---- stage2: span (80) | h1 (64) = 144 blocks, one wave ----
__global__ __launch_bounds__(256) void k_stage2(const int* __restrict__ seq_len) {
    extern __shared__ __align__(16) __nv_bfloat16 dyn[];
    __shared__ float red[256];
    int bx = blockIdx.x;
    if (bx < 80) {
        span_body(seq_len, bx % 10, bx / 10, dyn, dyn + NSTG * 64 * 32, red);
    } else {
        int idx = bx - 80;          // (n_t:2, m_t:4, ks:8)
        h1_body(idx & 1, (idx >> 1) & 3, idx >> 3, dyn, dyn + NSTG * 128 * 32);
    }
}

// fused tail: LN(relu) + h2 = h@Wp2^T+b2 + logits = h2@Lab^T + log-softmax CE
__global__ __launch_bounds__(256) void k_tail(const float* __restrict__ bp1,
                                              const float* __restrict__ gamma,
                                              const float* __restrict__ beta,
                                              const float* __restrict__ Wp2,
                                              const float* __restrict__ bp2,
                                              const float* __restrict__ lab,
                                              const int* __restrict__ chart,
                                              const int* __restrict__ action_len) {
    __shared__ float h[8][256];
    __shared__ float h2[8][256];
    __shared__ float lg[8][128];
    __shared__ float red[128];
    int tid = threadIdx.x;
    int r0 = blockIdx.x * 8;
    int warp = tid >> 5, lane = tid & 31;

    {
        int row = r0 + warp;
        int c0 = lane * 8;
        float x[8];
        #pragma unroll
        for (int j = 0; j < 8; j++) x[j] = bp1[c0 + j];
        #pragma unroll
        for (int p = 0; p < 8; p++) {
            const float* src = g_h1p + ((size_t)p * 512 + row) * 256 + c0;
            float4 v0 = *reinterpret_cast<const float4*>(src);
            float4 v1 = *reinterpret_cast<const float4*>(src + 4);
            x[0] += v0.x; x[1] += v0.y; x[2] += v0.z; x[3] += v0.w;
            x[4] += v1.x; x[5] += v1.y; x[6] += v1.z; x[7] += v1.w;
        }
        float sum = 0.f;
        #pragma unroll
        for (int j = 0; j < 8; j++) sum += x[j];
        #pragma unroll
        for (int o = 16; o; o >>= 1) sum += __shfl_xor_sync(0xffffffff, sum, o);
        float mean = sum * (1.0f / En);
        float s2 = 0.f;
        #pragma unroll
        for (int j = 0; j < 8; j++) { x[j] -= mean; s2 += x[j] * x[j]; }
        #pragma unroll
        for (int o = 16; o; o >>= 1) s2 += __shfl_xor_sync(0xffffffff, s2, o);
        float inv = rsqrtf(s2 * (1.0f / En) + 1e-5f);
        #pragma unroll
        for (int j = 0; j < 8; j++) {
            float y = x[j] * inv * gamma[c0 + j] + beta[c0 + j];
            h[warp][c0 + j] = fmaxf(y, 0.f);
        }
    }
    __syncthreads();
    {
        float acc[8] = {0, 0, 0, 0, 0, 0, 0, 0};
        const float4* wr = reinterpret_cast<const float4*>(Wp2 + (size_t)tid * 256);
        for (int k = 0; k < 64; k++) {
            float4 w = wr[k];
            #pragma unroll
            for (int r = 0; r < 8; r++)
                acc[r] += w.x * h[r][4 * k] + w.y * h[r][4 * k + 1]
                        + w.z * h[r][4 * k + 2] + w.w * h[r][4 * k + 3];
        }
        float bb = bp2[tid];
        #pragma unroll
        for (int r = 0; r < 8; r++) h2[r][tid] = acc[r] + bb;
    }
    __syncthreads();
    if (tid < 128) {
        float acc[8] = {0, 0, 0, 0, 0, 0, 0, 0};
        const float4* lr = reinterpret_cast<const float4*>(lab + (size_t)tid * 256);
        for (int k = 0; k < 64; k++) {
            float4 w = lr[k];
            #pragma unroll
            for (int r = 0; r < 8; r++)
                acc[r] += w.x * h2[r][4 * k] + w.y * h2[r][4 * k + 1]
                        + w.z * h2[r][4 * k + 2] + w.w * h2[r][4 * k + 3];
        }
        #pragma unroll
        for (int r = 0; r < 8; r++) lg[r][tid] = acc[r];
    }
    __syncthreads();
    for (int r = 0; r < 8; r++) {
        if (tid < 128) red[tid] = lg[r][tid];
        __syncthreads();
        for (int s = 64; s > 0; s >>= 1) { if (tid < s) red[tid] = fmaxf(red[tid], red[tid + s]); __syncthreads(); }
        float mx = red[0]; __syncthreads();
        if (tid < 128) red[tid] = expf(lg[r][tid] - mx);
        __syncthreads();
        for (int s = 64; s > 0; s >>= 1) { if (tid < s) red[tid] += red[tid + s]; __syncthreads(); }
        if (tid == 0) {
            int row = r0 + r;
            int b = row >> 6, a = row & 63;
            float lse = logf(red[0]);
            float ce = -(lg[r][chart[row]] - mx - lse);
            g_ce_part[row] = (a < action_len[b]) ? ce : 0.f;
        }
        __syncthreads();
    }
}

// final deterministic reduction
__global__ __launch_bounds__(512) void k_final(const int* __restrict__ action_len,
                                               float* __restrict__ out) {
    __shared__ float red[512];
    int tid = threadIdx.x;
    red[tid] = (tid < 80 ? g_span_sum[tid] : 0.f); __syncthreads();
    for (int s = 256; s > 0; s >>= 1) { if (tid < s) red[tid] += red[tid + s]; __syncthreads(); }
    float span_num = red[0]; __syncthreads();

    red[tid] = (tid < 80 ? g_span_cnt2[tid] : 0.f); __syncthreads();
    for (int s = 256; s > 0; s >>= 1) { if (tid < s) red[tid] += red[tid + s]; __syncthreads(); }
    float span_cnt = red[0]; __syncthreads();

    red[tid] = g_ce_part[tid]; __syncthreads();
    for (int s = 256; s > 0; s >>= 1) { if (tid < s) red[tid] += red[tid + s]; __syncthreads(); }
    float ce_sum = red[0];

    if (tid == 0) {
        int lc = 0;
        for (int b = 0; b < Bn; b++) lc += action_len[b];
        out[0] = span_num / span_cnt + ce_sum / (float)lc;
    }
}

// ===================== launch =====================
extern "C" void kernel_launch(void* const* d_in, const int* in_sizes, int n_in,
                              void* d_out, int out_size) {
    const float* reprs      = (const float*)d_in[0];
    const float* word_repr  = (const float*)d_in[1];
    const int*   seq_len    = (const int*)d_in[2];
    const int*   gold_span  = (const int*)d_in[3];
    const int*   span_start = (const int*)d_in[4];
    const int*   span_end   = (const int*)d_in[5];
    const int*   chart      = (const int*)d_in[6];
    const int*   action_len = (const int*)d_in[7];
    const float* Wb         = (const float*)d_in[8];
    const float* Wp1        = (const float*)d_in[9];
    const float* bp1        = (const float*)d_in[10];
    const float* gamma      = (const float*)d_in[11];
    const float* beta       = (const float*)d_in[12];
    const float* Wp2        = (const float*)d_in[13];
    const float* bp2        = (const float*)d_in[14];
    const float* lab        = (const float*)d_in[15];
    float* out = (float*)d_out;

    static bool attr_done = false;
    if (!attr_done) {
        cudaFuncSetAttribute(k_stage1, cudaFuncAttributeMaxDynamicSharedMemorySize, DYN_SMEM_128);
        cudaFuncSetAttribute(k_stage2, cudaFuncAttributeMaxDynamicSharedMemorySize, DYN_SMEM_128);
        attr_done = true;
    }

    // L0: conversions + W^T + bias column + bitmap zero
    k_prelude<<<CV_BLOCKS + WT_BLOCKS + 64 + 8, 256>>>(reprs, word_repr, Wp1, Wb);
    // L1: gemm1 || gold_repr || setbits
    k_stage1<<<648, 256, DYN_SMEM_128>>>(Wb, reprs, span_start, span_end, gold_span);
    // L2: span (64x64, 80 tiles) || h1 split-K=8
    k_stage2<<<144, 256, DYN_SMEM_128>>>(seq_len);
    // L3: fused LN + projector + CE
    k_tail<<<64, 256>>>(bp1, gamma, beta, Wp2, bp2, lab, chart, action_len);
    // L4: final reduction
    k_final<<<1, 512>>>(action_len, out);
}

// round 15
// speedup vs baseline: 1.4323x; 1.1379x over previous
// R15: byte-identical resubmission of R14 (k_tail rewrite). "container failed twice" is the
// known infra-side acquisition failure (R0 empty stub; R5/R6->R7 and R11->R13 both passed on resubmit).
#include <cuda_runtime.h>
#include <cuda_bf16.h>
#include <math.h>
#include <stdint.h>

// Problem constants
#define Bn   8
#define Ln   256
#define Dn   1024
#define An   64
#define Vn   128
#define En   256
#define Gn   2048
#define Wn   255
#define NEGV (-1000.0f)

// bf16 pack/unpack
__device__ __forceinline__ uint32_t pk2(float a, float b) {
    __nv_bfloat162 h; h.x = __float2bfloat16(a); h.y = __float2bfloat16(b);
    return *reinterpret_cast<uint32_t*>(&h);
}
__device__ __forceinline__ float2 upk2(uint32_t u) {
    __nv_bfloat162 h = *reinterpret_cast<__nv_bfloat162*>(&u);
    return __bfloat1622float2(h);
}
__device__ __forceinline__ uint32_t sm_u32(const void* p) {
    uint32_t a;
    asm("{ .reg .u64 t; cvta.to.shared.u64 t, %1; cvt.u32.u64 %0, t; }" : "=r"(a) : "l"(p));
    return a;
}

// warp mma: D(16x8,f32) += A(16x16,bf16,row) * B(16x8,bf16,col)
__device__ __forceinline__ void mma16816(float d[4], uint32_t a0, uint32_t a1,
                                         uint32_t a2, uint32_t a3,
                                         uint32_t b0, uint32_t b1) {
    asm volatile(
        "mma.sync.aligned.m16n8k16.row.col.f32.bf16.bf16.f32 "
        "{%0,%1,%2,%3}, {%4,%5,%6,%7}, {%8,%9}, {%0,%1,%2,%3};\n"
        : "+f"(d[0]), "+f"(d[1]), "+f"(d[2]), "+f"(d[3])
        : "r"(a0), "r"(a1), "r"(a2), "r"(a3), "r"(b0), "r"(b1));
}
__device__ __forceinline__ void ldsm_x4(uint32_t r[4], uint32_t addr) {
    asm volatile("ldmatrix.sync.aligned.m8n8.x4.shared.b16 {%0,%1,%2,%3}, [%4];\n"
                 : "=r"(r[0]), "=r"(r[1]), "=r"(r[2]), "=r"(r[3]) : "r"(addr));
}
__device__ __forceinline__ void cp16(uint32_t s_dst, const void* g_src) {
    asm volatile("cp.async.cg.shared.global [%0], [%1], 16;\n" :: "r"(s_dst), "l"(g_src));
}
#define CP_COMMIT() asm volatile("cp.async.commit_group;\n" ::: "memory")

// ===================== device scratch =====================
__device__ __align__(16) __nv_bfloat16 g_reprs_b[Bn * Ln * Dn];   // 4 MB
__device__ __align__(16) __nv_bfloat16 g_word_b[Bn * Wn * Dn];    // ~4 MB
__device__ __align__(16) __nv_bfloat16 g_Wp1b[En * 2 * Dn];       // 1 MB
__device__ __align__(16) __nv_bfloat16 g_Wt[Dn * Dn];             // W^T bf16, 2 MB
__device__ __align__(16) __nv_bfloat16 g_Tb[Bn * Ln * Dn];        // T bf16, 4 MB
__device__ float g_Tbias[Bn * Ln];                                 // T[:,1024] fp32
__device__ __align__(16) __nv_bfloat16 g_goldb[Bn * An * 2 * Dn]; // 2 MB
__device__ float g_h1p[8 * 512 * 256];                             // h1 split-K partials
__device__ __align__(16) uint32_t g_bitmap[Bn * Ln * Ln / 32];     // gold bitmap, 64 KB
__device__ float g_span_sum[80];
__device__ float g_span_cnt2[80];
__device__ float g_ce_part[512];

// ===================== merged prelude =====================
#define N_REPRS (Bn * Ln * Dn)        // 2097152
#define N_WORD  (Bn * Wn * Dn)        // 2088960
#define N_WP1   (En * 2 * Dn)         // 524288
#define CV_BLOCKS 2300
#define WT_BLOCKS 256
__global__ __launch_bounds__(256) void k_prelude(const float* __restrict__ reprs,
                                                 const float* __restrict__ word,
                                                 const float* __restrict__ wp1,
                                                 const float* __restrict__ Wb) {
    __shared__ float sh[64 * 65];
    int bx = blockIdx.x;
    if (bx < CV_BLOCKS) {
        size_t i = ((size_t)bx * 256 + threadIdx.x) * 8;
        const float* src; __nv_bfloat16* dst;
        if (i < N_REPRS) { src = reprs + i; dst = g_reprs_b + i; }
        else if (i < (size_t)N_REPRS + N_WORD) { size_t j = i - N_REPRS; src = word + j; dst = g_word_b + j; }
        else { size_t j = i - N_REPRS - N_WORD; src = wp1 + j; dst = g_Wp1b + j; }
        float4 a = *reinterpret_cast<const float4*>(src);
        float4 b = *reinterpret_cast<const float4*>(src + 4);
        uint4 o;
        o.x = pk2(a.x, a.y); o.y = pk2(a.z, a.w);
        o.z = pk2(b.x, b.y); o.w = pk2(b.z, b.w);
        *reinterpret_cast<uint4*>(dst) = o;
    } else if (bx < CV_BLOCKS + WT_BLOCKS) {
        int idx = bx - CV_BLOCKS;
        int n0 = (idx & 15) * 64, k0 = (idx >> 4) * 64;
        int r = threadIdx.x >> 2, cq = (threadIdx.x & 3) * 16;
        #pragma unroll
        for (int i = 0; i < 16; i++)
            sh[r * 65 + cq + i] = Wb[(size_t)(k0 + r) * 1025 + n0 + cq + i];
        __syncthreads();
        uint32_t pk[8];
        #pragma unroll
        for (int j = 0; j < 8; j++)
            pk[j] = pk2(sh[(cq + 2 * j) * 65 + r], sh[(cq + 2 * j + 1) * 65 + r]);
        __nv_bfloat16* dst = g_Wt + (size_t)(n0 + r) * 1024 + k0 + cq;
        *reinterpret_cast<uint4*>(dst)     = make_uint4(pk[0], pk[1], pk[2], pk[3]);
        *reinterpret_cast<uint4*>(dst + 8) = make_uint4(pk[4], pk[5], pk[6], pk[7]);
    } else if (bx < CV_BLOCKS + WT_BLOCKS + 64) {
        int idx = bx - CV_BLOCKS - WT_BLOCKS;
        float* wcol = sh;
        for (int i = threadIdx.x; i < 1024; i += 256) wcol[i] = Wb[(size_t)i * 1025 + 1024];
        __syncthreads();
        int wid = threadIdx.x >> 5, lane = threadIdx.x & 31;
        float wbias = Wb[(size_t)1024 * 1025 + 1024];
        #pragma unroll
        for (int rr = 0; rr < 4; rr++) {
            int row = idx * 32 + wid * 4 + rr;
            const float* ar = reprs + (size_t)row * 1024;
            float s = 0.f;
            for (int j = lane * 4; j < 1024; j += 128) {
                float4 a = *reinterpret_cast<const float4*>(ar + j);
                s += a.x * wcol[j] + a.y * wcol[j + 1] + a.z * wcol[j + 2] + a.w * wcol[j + 3];
            }
            #pragma unroll
            for (int o = 16; o; o >>= 1) s += __shfl_xor_sync(0xffffffff, s, o);
            if (lane == 0) g_Tbias[row] = s + wbias;
        }
    } else {
        int idx = (bx - CV_BLOCKS - WT_BLOCKS - 64) * 512 + threadIdx.x * 2;
        *reinterpret_cast<uint2*>(g_bitmap + idx) = make_uint2(0u, 0u);
    }
}

// ===================== HMMA NT mainloop: S-stage, swizzled 64B rows =====================
template<int BM, int BN, int MI, int NI, int S>
__device__ __forceinline__ void mma_nt_loop(
    const __nv_bfloat16* __restrict__ Ag, int lda, int m0,
    const __nv_bfloat16* __restrict__ Bg, int ldb, int n0,
    int kbeg, int kend, float acc[MI][NI][4],
    __nv_bfloat16* As, __nv_bfloat16* Bs)   // [S][BM*32], [S][BN*32]
{
    constexpr int WC = BN / (8 * NI);
    int tid = threadIdx.x;
    int lane = tid & 31, warp = tid >> 5;
    int wm = warp / WC, wn = warp % WC;

    int ldr = tid >> 2, seg = tid & 3;
    int sw = seg ^ ((ldr >> 1) & 3);
    const __nv_bfloat16* Arow = Ag + (size_t)(m0 + ldr) * lda + seg * 8;
    const __nv_bfloat16* Brow = Bg + (size_t)(n0 + ldr) * ldb + seg * 8;
    uint32_t sa_st = sm_u32(As) + ldr * 64 + sw * 16;
    uint32_t sb_st = sm_u32(Bs) + ldr * 64 + sw * 16;
    constexpr int AIT = BM / 64, BIT = BN / 64;
    constexpr uint32_t stA = (uint32_t)BM * 64;
    constexpr uint32_t stB = (uint32_t)BN * 64;

    int a_r = lane & 15;
    uint32_t a_base = sm_u32(As) + (uint32_t)(wm * MI * 16 + a_r) * 64;
    int xa = (a_r >> 1) & 3;
    int a_hi = lane >> 4;
    int b_r = (lane & 7) + 8 * (lane >> 4);
    uint32_t b_base = sm_u32(Bs) + (uint32_t)(wn * NI * 8 + b_r) * 64;
    int xb = (b_r >> 1) & 3;
    int b_hi = (lane >> 3) & 1;

    int nc = (kend - kbeg) >> 5;
    #pragma unroll
    for (int p = 0; p < S; p++) {
        if (p < nc) {
            int kc = kbeg + p * 32;
            #pragma unroll
            for (int it = 0; it < AIT; it++)
                cp16(sa_st + p * stA + it * 4096, Arow + (size_t)it * 64 * lda + kc);
            #pragma unroll
            for (int it = 0; it < BIT; it++)
                cp16(sb_st + p * stB + it * 4096, Brow + (size_t)it * 64 * ldb + kc);
        }
        CP_COMMIT();
    }

    for (int c = 0; c < nc; c++) {
        asm volatile("cp.async.wait_group %0;\n" :: "n"(S - 1) : "memory");
        __syncthreads();
        int st = c % S;
        uint32_t a0 = a_base + st * stA;
        uint32_t b0 = b_base + st * stB;
        #pragma unroll
        for (int kk = 0; kk < 2; kk++) {
            uint32_t af[MI][4], bfr[NI][2];
            #pragma unroll
            for (int mi = 0; mi < MI; mi++)
                ldsm_x4(af[mi], a0 + mi * 1024 + ((((kk * 2 + a_hi)) ^ xa) << 4));
            #pragma unroll
            for (int nj = 0; nj < NI / 2; nj++) {
                uint32_t br[4];
                ldsm_x4(br, b0 + nj * 1024 + ((((kk * 2 + b_hi)) ^ xb) << 4));
                bfr[2 * nj][0] = br[0]; bfr[2 * nj][1] = br[1];
                bfr[2 * nj + 1][0] = br[2]; bfr[2 * nj + 1][1] = br[3];
            }
            #pragma unroll
            for (int mi = 0; mi < MI; mi++)
                #pragma unroll
                for (int ni = 0; ni < NI; ni++)
                    mma16816(acc[mi][ni], af[mi][0], af[mi][1], af[mi][2], af[mi][3],
                             bfr[ni][0], bfr[ni][1]);
        }
        __syncthreads();
        if (c + S < nc) {
            int kc = kbeg + (c + S) * 32;
            #pragma unroll
            for (int it = 0; it < AIT; it++)
                cp16(sa_st + st * stA + it * 4096, Arow + (size_t)it * 64 * lda + kc);
            #pragma unroll
            for (int it = 0; it < BIT; it++)
                cp16(sb_st + st * stB + it * 4096, Brow + (size_t)it * 64 * ldb + kc);
        }
        CP_COMMIT();
    }
}

#define NSTG 5
#define DYN_SMEM_128 (NSTG * (128 + 128) * 32 * 2)   // 80 KB

// ---- stage1 sub-bodies ----
__device__ void gemm1_body(const float* __restrict__ Wb, int m_t, int n_t,
                           __nv_bfloat16* As, __nv_bfloat16* Bs) {
    float acc[4][4][4] = {};
    int m0 = m_t * 128, n0 = n_t * 128;
    mma_nt_loop<128, 128, 4, 4, NSTG>(g_reprs_b, 1024, m0, g_Wt, 1024, n0, 0, 1024, acc, As, Bs);
    int lane = threadIdx.x & 31, warp = threadIdx.x >> 5;
    int wm = warp >> 2, wn = warp & 3, g = lane >> 2, tg = lane & 3;
    const float* brow = Wb + (size_t)1024 * 1025;
    #pragma unroll
    for (int mi = 0; mi < 4; mi++) {
        int m = m0 + wm * 64 + mi * 16 + g;
        #pragma unroll
        for (int ni = 0; ni < 4; ni++) {
            int n = n0 + wn * 32 + ni * 8 + 2 * tg;
            float b0 = brow[n], b1 = brow[n + 1];
            *reinterpret_cast<uint32_t*>(g_Tb + (size_t)m * 1024 + n) =
                pk2(acc[mi][ni][0] + b0, acc[mi][ni][1] + b1);
            *reinterpret_cast<uint32_t*>(g_Tb + (size_t)(m + 8) * 1024 + n) =
                pk2(acc[mi][ni][2] + b0, acc[mi][ni][3] + b1);
        }
    }
}

__device__ void gold_repr_body(const float* __restrict__ reprs,
                               const int* __restrict__ span_start,
                               const int* __restrict__ span_end, int row) {
    int tid = threadIdx.x;
    int b = row >> 6;
    int s = span_start[row], e = span_end[row];
    const float4* rs = reinterpret_cast<const float4*>(reprs + ((size_t)b * Ln + s) * Dn);
    const float4* re = reinterpret_cast<const float4*>(reprs + ((size_t)b * Ln + e) * Dn);
    float4 a = re[tid], c = rs[tid];
    uint2 o;
    o.x = pk2(a.x - c.x, a.y - c.y);
    o.y = pk2(a.z - c.z, a.w - c.w);
    *reinterpret_cast<uint2*>(g_goldb + (size_t)row * 2048 + tid * 4) = o;

    float m0 = NEGV, m1 = NEGV, m2 = NEGV, m3 = NEGV;
    float n0 = NEGV, n1 = NEGV, n2 = NEGV, n3 = NEGV;
    const __nv_bfloat16* wb = g_word_b + (size_t)b * Wn * Dn + tid * 4;
    int ee = min(e, Wn);
    int w = s;
    for (; w + 1 < ee; w += 2) {
        uint2 v0 = *reinterpret_cast<const uint2*>(wb + (size_t)w * Dn);
        uint2 v1 = *reinterpret_cast<const uint2*>(wb + (size_t)(w + 1) * Dn);
        float2 a0 = upk2(v0.x), a1 = upk2(v0.y);
        float2 b0 = upk2(v1.x), b1 = upk2(v1.y);
        m0 = fmaxf(m0, a0.x); m1 = fmaxf(m1, a0.y);
        m2 = fmaxf(m2, a1.x); m3 = fmaxf(m3, a1.y);
        n0 = fmaxf(n0, b0.x); n1 = fmaxf(n1, b0.y);
        n2 = fmaxf(n2, b1.x); n3 = fmaxf(n3, b1.y);
    }
    if (w < ee) {
        uint2 v0 = *reinterpret_cast<const uint2*>(wb + (size_t)w * Dn);
        float2 a0 = upk2(v0.x), a1 = upk2(v0.y);
        m0 = fmaxf(m0, a0.x); m1 = fmaxf(m1, a0.y);
        m2 = fmaxf(m2, a1.x); m3 = fmaxf(m3, a1.y);
    }
    m0 = fmaxf(m0, n0); m1 = fmaxf(m1, n1); m2 = fmaxf(m2, n2); m3 = fmaxf(m3, n3);
    uint2 p; p.x = pk2(m0, m1); p.y = pk2(m2, m3);
    *reinterpret_cast<uint2*>(g_goldb + (size_t)row * 2048 + 1024 + tid * 4) = p;
}

// ---- stage1: gemm1 (128) | gold_repr (512) | setbits (8) ----
__global__ __launch_bounds__(256) void k_stage1(const float* __restrict__ Wb,
                                                const float* __restrict__ reprs,
                                                const int* __restrict__ span_start,
                                                const int* __restrict__ span_end,
                                                const int* __restrict__ gold) {
    extern __shared__ __align__(16) __nv_bfloat16 dyn[];
    int bx = blockIdx.x;
    if (bx < 128) {
        gemm1_body(Wb, bx >> 3, bx & 7, dyn, dyn + NSTG * 128 * 32);
    } else if (bx < 640) {
        gold_repr_body(reprs, span_start, span_end, bx - 128);
    } else {
        int g = (bx - 640) * 256 + threadIdx.x;
        int gb = gold[3 * g], gl = gold[3 * g + 1], gr = gold[3 * g + 2];
        int idx = (gb << 16) | (gl << 8) | gr;
        atomicOr(&g_bitmap[idx >> 5], 1u << (idx & 31));
    }
}

// ---- stage2 sub-bodies ----
__constant__ int c_xt[10] = {0, 0, 0, 0, 1, 1, 1, 2, 2, 3};
__constant__ int c_yt[10] = {0, 1, 2, 3, 1, 2, 3, 2, 3, 3};

__device__ void span_body(const int* __restrict__ seq_len, int t, int b,
                          __nv_bfloat16* As, __nv_bfloat16* Bs, float* red) {
    int x0 = c_xt[t] * 64, y0 = c_yt[t] * 64;
    int slot = b * 10 + t;
    int sl = seq_len[b];
    int tid = threadIdx.x;
    if (y0 > sl) {
        if (tid == 0) { g_span_sum[slot] = 0.f; g_span_cnt2[slot] = 0.f; }
        return;
    }
    float acc[2][2][4] = {};
    mma_nt_loop<64, 64, 2, 2, NSTG>(g_Tb + (size_t)b * Ln * Dn, 1024, x0,
                                    g_reprs_b + (size_t)b * Ln * Dn, 1024, y0, 0, 1024, acc, As, Bs);
    int lane = tid & 31, warp = tid >> 5;
    int wm = warp >> 2, wn = warp & 3, g = lane >> 2, tg = lane & 3;
    float lsum = 0.f, lcnt = 0.f;
    #pragma unroll
    for (int mi = 0; mi < 2; mi++) {
        int xA = x0 + wm * 32 + mi * 16 + g;
        int xB = xA + 8;
        float tbA = g_Tbias[b * Ln + xA];
        float tbB = g_Tbias[b * Ln + xB];
        #pragma unroll
        for (int ni = 0; ni < 2; ni++) {
            int y = y0 + wn * 16 + ni * 8 + 2 * tg;
            #pragma unroll
            for (int e = 0; e < 4; e++) {
                int yy = y + (e & 1);
                int xx = (e < 2) ? xA : xB;
                float tb = (e < 2) ? tbA : tbB;
                if (yy > xx && yy <= sl) {
                    float s = acc[mi][ni][e] + tb;
                    lsum += fmaxf(s, 0.f) + log1pf(expf(-fabsf(s)));
                    int idx = (b << 16) | (xx << 8) | yy;
                    if ((g_bitmap[idx >> 5] >> (idx & 31)) & 1u) lsum -= s;
                    lcnt += 1.f;
                }
            }
        }
    }
    red[tid] = lsum; __syncthreads();
    for (int s = 128; s > 0; s >>= 1) { if (tid < s) red[tid] += red[tid + s]; __syncthreads(); }
    float tot = red[0]; __syncthreads();
    red[tid] = lcnt; __syncthreads();
    for (int s = 128; s > 0; s >>= 1) { if (tid < s) red[tid] += red[tid + s]; __syncthreads(); }
    if (tid == 0) { g_span_sum[slot] = tot; g_span_cnt2[slot] = red[0]; }
}

__device__ void h1_body(int n_t, int m_t, int ks, __nv_bfloat16* As, __nv_bfloat16* Bs) {
    float acc[4][4][4] = {};
    int n0 = n_t * 128, m0 = m_t * 128;
    mma_nt_loop<128, 128, 4, 4, NSTG>(g_goldb, 2048, m0, g_Wp1b, 2048, n0,
                                      ks * 256, ks * 256 + 256, acc, As, Bs);
    int lane = threadIdx.x & 31, warp = threadIdx.x >> 5;
    int wm = warp >> 2, wn = warp & 3, g = lane >> 2, tg = lane & 3;
    float* dst = g_h1p + (size_t)ks * 512 * 256;
    #pragma unroll
    for (int mi = 0; mi < 4; mi++) {
        int m = m0 + wm * 64 + mi * 16 + g;
        #pragma unroll
        for (int ni = 0; ni < 4; ni++) {
            int n = n0 + wn * 32 + ni * 8 + 2 * tg;
            *reinterpret_cast<float2*>(dst + (size_t)m * 256 + n) =
                make_float2(acc[mi][ni][0], acc[mi][ni][1]);
            *reinterpret_cast<float2*>(dst + (size_t)(m + 8) * 256 + n) =
                make_float2(acc[mi][ni][2], acc[mi][ni][3]);
        }
    }
}

// ---- stage2: span (80) | h1 (64) = 144 blocks, one wave ----
__global__ __launch_bounds__(256) void k_stage2(const int* __restrict__ seq_len) {
    extern __shared__ __align__(16) __nv_bfloat16 dyn[];
    __shared__ float red[256];
    int bx = blockIdx.x;
    if (bx < 80) {
        span_body(seq_len, bx % 10, bx / 10, dyn, dyn + NSTG * 64 * 32, red);
    } else {
        int idx = bx - 80;          // (n_t:2, m_t:4, ks:8)
        h1_body(idx & 1, (idx >> 1) & 3, idx >> 3, dyn, dyn + NSTG * 128 * 32);
    }
}

// fused tail: LN(relu) + h2 + logits + warp-softmax CE
__global__ __launch_bounds__(256) void k_tail(const float* __restrict__ bp1,
                                              const float* __restrict__ gamma,
                                              const float* __restrict__ beta,
                                              const float* __restrict__ Wp2,
                                              const float* __restrict__ bp2,
                                              const float* __restrict__ lab,
                                              const int* __restrict__ chart,
                                              const int* __restrict__ action_len) {
    __shared__ float h[8][256];
    __shared__ float h2s[8][256];
    __shared__ float lg[8][128];
    int tid = threadIdx.x;
    int r0 = blockIdx.x * 8;
    int warp = tid >> 5, lane = tid & 31;

    // --- LN: warp r handles row r0+r, lane covers 8 cols (MLP-8 partial loads) ---
    {
        int row = r0 + warp;
        int c0 = lane * 8;
        float x[8];
        #pragma unroll
        for (int j = 0; j < 8; j++) x[j] = bp1[c0 + j];
        #pragma unroll
        for (int p = 0; p < 8; p++) {
            const float* src = g_h1p + ((size_t)p * 512 + row) * 256 + c0;
            float4 v0 = *reinterpret_cast<const float4*>(src);
            float4 v1 = *reinterpret_cast<const float4*>(src + 4);
            x[0] += v0.x; x[1] += v0.y; x[2] += v0.z; x[3] += v0.w;
            x[4] += v1.x; x[5] += v1.y; x[6] += v1.z; x[7] += v1.w;
        }
        float sum = 0.f;
        #pragma unroll
        for (int j = 0; j < 8; j++) sum += x[j];
        #pragma unroll
        for (int o = 16; o; o >>= 1) sum += __shfl_xor_sync(0xffffffff, sum, o);
        float mean = sum * (1.0f / En);
        float s2 = 0.f;
        #pragma unroll
        for (int j = 0; j < 8; j++) { x[j] -= mean; s2 += x[j] * x[j]; }
        #pragma unroll
        for (int o = 16; o; o >>= 1) s2 += __shfl_xor_sync(0xffffffff, s2, o);
        float inv = rsqrtf(s2 * (1.0f / En) + 1e-5f);
        #pragma unroll
        for (int j = 0; j < 8; j++) {
            float y = x[j] * inv * gamma[c0 + j] + beta[c0 + j];
            h[warp][c0 + j] = fmaxf(y, 0.f);
        }
    }
    __syncthreads();

    // --- h2[r][tid] = h[r] . Wp2[tid] + bp2[tid], unroll-8 on the Wp2 stream ---
    {
        float acc[8] = {0, 0, 0, 0, 0, 0, 0, 0};
        const float4* wr = reinterpret_cast<const float4*>(Wp2 + (size_t)tid * 256);
        #pragma unroll 8
        for (int k = 0; k < 64; k++) {
            float4 w = wr[k];
            #pragma unroll
            for (int r = 0; r < 8; r++) {
                float4 hv = *reinterpret_cast<const float4*>(&h[r][4 * k]);
                acc[r] += w.x * hv.x + w.y * hv.y + w.z * hv.z + w.w * hv.w;
            }
        }
        float bb = bp2[tid];
        #pragma unroll
        for (int r = 0; r < 8; r++) h2s[r][tid] = acc[r] + bb;
    }
    __syncthreads();

    // --- logits: all 256 threads; t<128 -> rows 0..3 col t; t>=128 -> rows 4..7 col t-128 ---
    {
        int col = tid & 127;
        int rb = (tid >> 7) * 4;
        float acc[4] = {0, 0, 0, 0};
        const float4* lr = reinterpret_cast<const float4*>(lab + (size_t)col * 256);
        #pragma unroll 8
        for (int k = 0; k < 64; k++) {
            float4 w = lr[k];
            #pragma unroll
            for (int r = 0; r < 4; r++) {
                float4 hv = *reinterpret_cast<const float4*>(&h2s[rb + r][4 * k]);
                acc[r] += w.x * hv.x + w.y * hv.y + w.z * hv.z + w.w * hv.w;
            }
        }
        #pragma unroll
        for (int r = 0; r < 4; r++) lg[rb + r][col] = acc[r];
    }
    __syncthreads();

    // --- softmax + CE: warp r handles row r0+r, shuffle reductions only ---
    {
        int r = warp;
        int row = r0 + r;
        float v0 = lg[r][lane], v1 = lg[r][lane + 32];
        float v2 = lg[r][lane + 64], v3 = lg[r][lane + 96];
        float mx = fmaxf(fmaxf(v0, v1), fmaxf(v2, v3));
        #pragma unroll
        for (int o = 16; o; o >>= 1) mx = fmaxf(mx, __shfl_xor_sync(0xffffffff, mx, o));
        float sum = expf(v0 - mx) + expf(v1 - mx) + expf(v2 - mx) + expf(v3 - mx);
        #pragma unroll
        for (int o = 16; o; o >>= 1) sum += __shfl_xor_sync(0xffffffff, sum, o);
        if (lane == 0) {
            float lse = logf(sum);
            int c = chart[row];
            float ce = -(lg[r][c] - mx - lse);
            int b = row >> 6, a = row & 63;
            g_ce_part[row] = (a < action_len[b]) ? ce : 0.f;
        }
    }
}

// final deterministic reduction
__global__ __launch_bounds__(512) void k_final(const int* __restrict__ action_len,
                                               float* __restrict__ out) {
    __shared__ float red[512];
    int tid = threadIdx.x;
    red[tid] = (tid < 80 ? g_span_sum[tid] : 0.f); __syncthreads();
    for (int s = 256; s > 0; s >>= 1) { if (tid < s) red[tid] += red[tid + s]; __syncthreads(); }
    float span_num = red[0]; __syncthreads();

    red[tid] = (tid < 80 ? g_span_cnt2[tid] : 0.f); __syncthreads();
    for (int s = 256; s > 0; s >>= 1) { if (tid < s) red[tid] += red[tid + s]; __syncthreads(); }
    float span_cnt = red[0]; __syncthreads();

    red[tid] = g_ce_part[tid]; __syncthreads();
    for (int s = 256; s > 0; s >>= 1) { if (tid < s) red[tid] += red[tid + s]; __syncthreads(); }
    float ce_sum = red[0];

    if (tid == 0) {
        int lc = 0;
        for (int b = 0; b < Bn; b++) lc += action_len[b];
        out[0] = span_num / span_cnt + ce_sum / (float)lc;
    }
}

// ===================== launch =====================
extern "C" void kernel_launch(void* const* d_in, const int* in_sizes, int n_in,
                              void* d_out, int out_size) {
    const float* reprs      = (const float*)d_in[0];
    const float* word_repr  = (const float*)d_in[1];
    const int*   seq_len    = (const int*)d_in[2];
    const int*   gold_span  = (const int*)d_in[3];
    const int*   span_start = (const int*)d_in[4];
    const int*   span_end   = (const int*)d_in[5];
    const int*   chart      = (const int*)d_in[6];
    const int*   action_len = (const int*)d_in[7];
    const float* Wb         = (const float*)d_in[8];
    const float* Wp1        = (const float*)d_in[9];
    const float* bp1        = (const float*)d_in[10];
    const float* gamma      = (const float*)d_in[11];
    const float* beta       = (const float*)d_in[12];
    const float* Wp2        = (const float*)d_in[13];
    const float* bp2        = (const float*)d_in[14];
    const float* lab        = (const float*)d_in[15];
    float* out = (float*)d_out;

    static bool attr_done = false;
    if (!attr_done) {
        cudaFuncSetAttribute(k_stage1, cudaFuncAttributeMaxDynamicSharedMemorySize, DYN_SMEM_128);
        cudaFuncSetAttribute(k_stage2, cudaFuncAttributeMaxDynamicSharedMemorySize, DYN_SMEM_128);
        attr_done = true;
    }

    // L0: conversions + W^T + bias column + bitmap zero
    k_prelude<<<CV_BLOCKS + WT_BLOCKS + 64 + 8, 256>>>(reprs, word_repr, Wp1, Wb);
    // L1: gemm1 || gold_repr || setbits
    k_stage1<<<648, 256, DYN_SMEM_128>>>(Wb, reprs, span_start, span_end, gold_span);
    // L2: span (64x64, 80 tiles) || h1 split-K=8
    k_stage2<<<144, 256, DYN_SMEM_128>>>(seq_len);
    // L3: fused LN + projector + CE (rewritten: MLP-8, warp softmax)
    k_tail<<<64, 256>>>(bp1, gamma, beta, Wp2, bp2, lab, chart, action_len);
    // L4: final reduction
    k_final<<<1, 512>>>(action_len, out);
}

// round 16
// speedup vs baseline: 1.4759x; 1.0304x over previous
// R16: k_tail re-gridded 64 blocks x 8 rows -> 128 blocks x 4 rows (was leaving 84 SMs idle;
// per-thread FFMA halves). All other kernels byte-identical to R15 (88.9us).
#include <cuda_runtime.h>
#include <cuda_bf16.h>
#include <math.h>
#include <stdint.h>

// Problem constants
#define Bn   8
#define Ln   256
#define Dn   1024
#define An   64
#define Vn   128
#define En   256
#define Gn   2048
#define Wn   255
#define NEGV (-1000.0f)

// bf16 pack/unpack
__device__ __forceinline__ uint32_t pk2(float a, float b) {
    __nv_bfloat162 h; h.x = __float2bfloat16(a); h.y = __float2bfloat16(b);
    return *reinterpret_cast<uint32_t*>(&h);
}
__device__ __forceinline__ float2 upk2(uint32_t u) {
    __nv_bfloat162 h = *reinterpret_cast<__nv_bfloat162*>(&u);
    return __bfloat1622float2(h);
}
__device__ __forceinline__ uint32_t sm_u32(const void* p) {
    uint32_t a;
    asm("{ .reg .u64 t; cvta.to.shared.u64 t, %1; cvt.u32.u64 %0, t; }" : "=r"(a) : "l"(p));
    return a;
}

// warp mma: D(16x8,f32) += A(16x16,bf16,row) * B(16x8,bf16,col)
__device__ __forceinline__ void mma16816(float d[4], uint32_t a0, uint32_t a1,
                                         uint32_t a2, uint32_t a3,
                                         uint32_t b0, uint32_t b1) {
    asm volatile(
        "mma.sync.aligned.m16n8k16.row.col.f32.bf16.bf16.f32 "
        "{%0,%1,%2,%3}, {%4,%5,%6,%7}, {%8,%9}, {%0,%1,%2,%3};\n"
        : "+f"(d[0]), "+f"(d[1]), "+f"(d[2]), "+f"(d[3])
        : "r"(a0), "r"(a1), "r"(a2), "r"(a3), "r"(b0), "r"(b1));
}
__device__ __forceinline__ void ldsm_x4(uint32_t r[4], uint32_t addr) {
    asm volatile("ldmatrix.sync.aligned.m8n8.x4.shared.b16 {%0,%1,%2,%3}, [%4];\n"
                 : "=r"(r[0]), "=r"(r[1]), "=r"(r[2]), "=r"(r[3]) : "r"(addr));
}
__device__ __forceinline__ void cp16(uint32_t s_dst, const void* g_src) {
    asm volatile("cp.async.cg.shared.global [%0], [%1], 16;\n" :: "r"(s_dst), "l"(g_src));
}
#define CP_COMMIT() asm volatile("cp.async.commit_group;\n" ::: "memory")

// ===================== device scratch =====================
__device__ __align__(16) __nv_bfloat16 g_reprs_b[Bn * Ln * Dn];   // 4 MB
__device__ __align__(16) __nv_bfloat16 g_word_b[Bn * Wn * Dn];    // ~4 MB
__device__ __align__(16) __nv_bfloat16 g_Wp1b[En * 2 * Dn];       // 1 MB
__device__ __align__(16) __nv_bfloat16 g_Wt[Dn * Dn];             // W^T bf16, 2 MB
__device__ __align__(16) __nv_bfloat16 g_Tb[Bn * Ln * Dn];        // T bf16, 4 MB
__device__ float g_Tbias[Bn * Ln];                                 // T[:,1024] fp32
__device__ __align__(16) __nv_bfloat16 g_goldb[Bn * An * 2 * Dn]; // 2 MB
__device__ float g_h1p[8 * 512 * 256];                             // h1 split-K partials
__device__ __align__(16) uint32_t g_bitmap[Bn * Ln * Ln / 32];     // gold bitmap, 64 KB
__device__ float g_span_sum[80];
__device__ float g_span_cnt2[80];
__device__ float g_ce_part[512];

// ===================== merged prelude =====================
#define N_REPRS (Bn * Ln * Dn)        // 2097152
#define N_WORD  (Bn * Wn * Dn)        // 2088960
#define N_WP1   (En * 2 * Dn)         // 524288
#define CV_BLOCKS 2300
#define WT_BLOCKS 256
__global__ __launch_bounds__(256) void k_prelude(const float* __restrict__ reprs,
                                                 const float* __restrict__ word,
                                                 const float* __restrict__ wp1,
                                                 const float* __restrict__ Wb) {
    __shared__ float sh[64 * 65];
    int bx = blockIdx.x;
    if (bx < CV_BLOCKS) {
        size_t i = ((size_t)bx * 256 + threadIdx.x) * 8;
        const float* src; __nv_bfloat16* dst;
        if (i < N_REPRS) { src = reprs + i; dst = g_reprs_b + i; }
        else if (i < (size_t)N_REPRS + N_WORD) { size_t j = i - N_REPRS; src = word + j; dst = g_word_b + j; }
        else { size_t j = i - N_REPRS - N_WORD; src = wp1 + j; dst = g_Wp1b + j; }
        float4 a = *reinterpret_cast<const float4*>(src);
        float4 b = *reinterpret_cast<const float4*>(src + 4);
        uint4 o;
        o.x = pk2(a.x, a.y); o.y = pk2(a.z, a.w);
        o.z = pk2(b.x, b.y); o.w = pk2(b.z, b.w);
        *reinterpret_cast<uint4*>(dst) = o;
    } else if (bx < CV_BLOCKS + WT_BLOCKS) {
        int idx = bx - CV_BLOCKS;
        int n0 = (idx & 15) * 64, k0 = (idx >> 4) * 64;
        int r = threadIdx.x >> 2, cq = (threadIdx.x & 3) * 16;
        #pragma unroll
        for (int i = 0; i < 16; i++)
            sh[r * 65 + cq + i] = Wb[(size_t)(k0 + r) * 1025 + n0 + cq + i];
        __syncthreads();
        uint32_t pk[8];
        #pragma unroll
        for (int j = 0; j < 8; j++)
            pk[j] = pk2(sh[(cq + 2 * j) * 65 + r], sh[(cq + 2 * j + 1) * 65 + r]);
        __nv_bfloat16* dst = g_Wt + (size_t)(n0 + r) * 1024 + k0 + cq;
        *reinterpret_cast<uint4*>(dst)     = make_uint4(pk[0], pk[1], pk[2], pk[3]);
        *reinterpret_cast<uint4*>(dst + 8) = make_uint4(pk[4], pk[5], pk[6], pk[7]);
    } else if (bx < CV_BLOCKS + WT_BLOCKS + 64) {
        int idx = bx - CV_BLOCKS - WT_BLOCKS;
        float* wcol = sh;
        for (int i = threadIdx.x; i < 1024; i += 256) wcol[i] = Wb[(size_t)i * 1025 + 1024];
        __syncthreads();
        int wid = threadIdx.x >> 5, lane = threadIdx.x & 31;
        float wbias = Wb[(size_t)1024 * 1025 + 1024];
        #pragma unroll
        for (int rr = 0; rr < 4; rr++) {
            int row = idx * 32 + wid * 4 + rr;
            const float* ar = reprs + (size_t)row * 1024;
            float s = 0.f;
            for (int j = lane * 4; j < 1024; j += 128) {
                float4 a = *reinterpret_cast<const float4*>(ar + j);
                s += a.x * wcol[j] + a.y * wcol[j + 1] + a.z * wcol[j + 2] + a.w * wcol[j + 3];
            }
            #pragma unroll
            for (int o = 16; o; o >>= 1) s += __shfl_xor_sync(0xffffffff, s, o);
            if (lane == 0) g_Tbias[row] = s + wbias;
        }
    } else {
        int idx = (bx - CV_BLOCKS - WT_BLOCKS - 64) * 512 + threadIdx.x * 2;
        *reinterpret_cast<uint2*>(g_bitmap + idx) = make_uint2(0u, 0u);
    }
}

// ===================== HMMA NT mainloop: S-stage, swizzled 64B rows =====================
template<int BM, int BN, int MI, int NI, int S>
__device__ __forceinline__ void mma_nt_loop(
    const __nv_bfloat16* __restrict__ Ag, int lda, int m0,
    const __nv_bfloat16* __restrict__ Bg, int ldb, int n0,
    int kbeg, int kend, float acc[MI][NI][4],
    __nv_bfloat16* As, __nv_bfloat16* Bs)   // [S][BM*32], [S][BN*32]
{
    constexpr int WC = BN / (8 * NI);
    int tid = threadIdx.x;
    int lane = tid & 31, warp = tid >> 5;
    int wm = warp / WC, wn = warp % WC;

    int ldr = tid >> 2, seg = tid & 3;
    int sw = seg ^ ((ldr >> 1) & 3);
    const __nv_bfloat16* Arow = Ag + (size_t)(m0 + ldr) * lda + seg * 8;
    const __nv_bfloat16* Brow = Bg + (size_t)(n0 + ldr) * ldb + seg * 8;
    uint32_t sa_st = sm_u32(As) + ldr * 64 + sw * 16;
    uint32_t sb_st = sm_u32(Bs) + ldr * 64 + sw * 16;
    constexpr int AIT = BM / 64, BIT = BN / 64;
    constexpr uint32_t stA = (uint32_t)BM * 64;
    constexpr uint32_t stB = (uint32_t)BN * 64;

    int a_r = lane & 15;
    uint32_t a_base = sm_u32(As) + (uint32_t)(wm * MI * 16 + a_r) * 64;
    int xa = (a_r >> 1) & 3;
    int a_hi = lane >> 4;
    int b_r = (lane & 7) + 8 * (lane >> 4);
    uint32_t b_base = sm_u32(Bs) + (uint32_t)(wn * NI * 8 + b_r) * 64;
    int xb = (b_r >> 1) & 3;
    int b_hi = (lane >> 3) & 1;

    int nc = (kend - kbeg) >> 5;
    #pragma unroll
    for (int p = 0; p < S; p++) {
        if (p < nc) {
            int kc = kbeg + p * 32;
            #pragma unroll
            for (int it = 0; it < AIT; it++)
                cp16(sa_st + p * stA + it * 4096, Arow + (size_t)it * 64 * lda + kc);
            #pragma unroll
            for (int it = 0; it < BIT; it++)
                cp16(sb_st + p * stB + it * 4096, Brow + (size_t)it * 64 * ldb + kc);
        }
        CP_COMMIT();
    }

    for (int c = 0; c < nc; c++) {
        asm volatile("cp.async.wait_group %0;\n" :: "n"(S - 1) : "memory");
        __syncthreads();
        int st = c % S;
        uint32_t a0 = a_base + st * stA;
        uint32_t b0 = b_base + st * stB;
        #pragma unroll
        for (int kk = 0; kk < 2; kk++) {
            uint32_t af[MI][4], bfr[NI][2];
            #pragma unroll
            for (int mi = 0; mi < MI; mi++)
                ldsm_x4(af[mi], a0 + mi * 1024 + ((((kk * 2 + a_hi)) ^ xa) << 4));
            #pragma unroll
            for (int nj = 0; nj < NI / 2; nj++) {
                uint32_t br[4];
                ldsm_x4(br, b0 + nj * 1024 + ((((kk * 2 + b_hi)) ^ xb) << 4));
                bfr[2 * nj][0] = br[0]; bfr[2 * nj][1] = br[1];
                bfr[2 * nj + 1][0] = br[2]; bfr[2 * nj + 1][1] = br[3];
            }
            #pragma unroll
            for (int mi = 0; mi < MI; mi++)
                #pragma unroll
                for (int ni = 0; ni < NI; ni++)
                    mma16816(acc[mi][ni], af[mi][0], af[mi][1], af[mi][2], af[mi][3],
                             bfr[ni][0], bfr[ni][1]);
        }
        __syncthreads();
        if (c + S < nc) {
            int kc = kbeg + (c + S) * 32;
            #pragma unroll
            for (int it = 0; it < AIT; it++)
                cp16(sa_st + st * stA + it * 4096, Arow + (size_t)it * 64 * lda + kc);
            #pragma unroll
            for (int it = 0; it < BIT; it++)
                cp16(sb_st + st * stB + it * 4096, Brow + (size_t)it * 64 * ldb + kc);
        }
        CP_COMMIT();
    }
}

#define NSTG 5
#define DYN_SMEM_128 (NSTG * (128 + 128) * 32 * 2)   // 80 KB

// ---- stage1 sub-bodies ----
__device__ void gemm1_body(const float* __restrict__ Wb, int m_t, int n_t,
                           __nv_bfloat16* As, __nv_bfloat16* Bs) {
    float acc[4][4][4] = {};
    int m0 = m_t * 128, n0 = n_t * 128;
    mma_nt_loop<128, 128, 4, 4, NSTG>(g_reprs_b, 1024, m0, g_Wt, 1024, n0, 0, 1024, acc, As, Bs);
    int lane = threadIdx.x & 31, warp = threadIdx.x >> 5;
    int wm = warp >> 2, wn = warp & 3, g = lane >> 2, tg = lane & 3;
    const float* brow = Wb + (size_t)1024 * 1025;
    #pragma unroll
    for (int mi = 0; mi < 4; mi++) {
        int m = m0 + wm * 64 + mi * 16 + g;
        #pragma unroll
        for (int ni = 0; ni < 4; ni++) {
            int n = n0 + wn * 32 + ni * 8 + 2 * tg;
            float b0 = brow[n], b1 = brow[n + 1];
            *reinterpret_cast<uint32_t*>(g_Tb + (size_t)m * 1024 + n) =
                pk2(acc[mi][ni][0] + b0, acc[mi][ni][1] + b1);
            *reinterpret_cast<uint32_t*>(g_Tb + (size_t)(m + 8) * 1024 + n) =
                pk2(acc[mi][ni][2] + b0, acc[mi][ni][3] + b1);
        }
    }
}

__device__ void gold_repr_body(const float* __restrict__ reprs,
                               const int* __restrict__ span_start,
                               const int* __restrict__ span_end, int row) {
    int tid = threadIdx.x;
    int b = row >> 6;
    int s = span_start[row], e = span_end[row];
    const float4* rs = reinterpret_cast<const float4*>(reprs + ((size_t)b * Ln + s) * Dn);
    const float4* re = reinterpret_cast<const float4*>(reprs + ((size_t)b * Ln + e) * Dn);
    float4 a = re[tid], c = rs[tid];
    uint2 o;
    o.x = pk2(a.x - c.x, a.y - c.y);
    o.y = pk2(a.z - c.z, a.w - c.w);
    *reinterpret_cast<uint2*>(g_goldb + (size_t)row * 2048 + tid * 4) = o;

    float m0 = NEGV, m1 = NEGV, m2 = NEGV, m3 = NEGV;
    float n0 = NEGV, n1 = NEGV, n2 = NEGV, n3 = NEGV;
    const __nv_bfloat16* wb = g_word_b + (size_t)b * Wn * Dn + tid * 4;
    int ee = min(e, Wn);
    int w = s;
    for (; w + 1 < ee; w += 2) {
        uint2 v0 = *reinterpret_cast<const uint2*>(wb + (size_t)w * Dn);
        uint2 v1 = *reinterpret_cast<const uint2*>(wb + (size_t)(w + 1) * Dn);
        float2 a0 = upk2(v0.x), a1 = upk2(v0.y);
        float2 b0 = upk2(v1.x), b1 = upk2(v1.y);
        m0 = fmaxf(m0, a0.x); m1 = fmaxf(m1, a0.y);
        m2 = fmaxf(m2, a1.x); m3 = fmaxf(m3, a1.y);
        n0 = fmaxf(n0, b0.x); n1 = fmaxf(n1, b0.y);
        n2 = fmaxf(n2, b1.x); n3 = fmaxf(n3, b1.y);
    }
    if (w < ee) {
        uint2 v0 = *reinterpret_cast<const uint2*>(wb + (size_t)w * Dn);
        float2 a0 = upk2(v0.x), a1 = upk2(v0.y);
        m0 = fmaxf(m0, a0.x); m1 = fmaxf(m1, a0.y);
        m2 = fmaxf(m2, a1.x); m3 = fmaxf(m3, a1.y);
    }
    m0 = fmaxf(m0, n0); m1 = fmaxf(m1, n1); m2 = fmaxf(m2, n2); m3 = fmaxf(m3, n3);
    uint2 p; p.x = pk2(m0, m1); p.y = pk2(m2, m3);
    *reinterpret_cast<uint2*>(g_goldb + (size_t)row * 2048 + 1024 + tid * 4) = p;
}

// ---- stage1: gemm1 (128) | gold_repr (512) | setbits (8) ----
__global__ __launch_bounds__(256) void k_stage1(const float* __restrict__ Wb,
                                                const float* __restrict__ reprs,
                                                const int* __restrict__ span_start,
                                                const int* __restrict__ span_end,
                                                const int* __restrict__ gold) {
    extern __shared__ __align__(16) __nv_bfloat16 dyn[];
    int bx = blockIdx.x;
    if (bx < 128) {
        gemm1_body(Wb, bx >> 3, bx & 7, dyn, dyn + NSTG * 128 * 32);
    } else if (bx < 640) {
        gold_repr_body(reprs, span_start, span_end, bx - 128);
    } else {
        int g = (bx - 640) * 256 + threadIdx.x;
        int gb = gold[3 * g], gl = gold[3 * g + 1], gr = gold[3 * g + 2];
        int idx = (gb << 16) | (gl << 8) | gr;
        atomicOr(&g_bitmap[idx >> 5], 1u << (idx & 31));
    }
}

// ---- stage2 sub-bodies ----
__constant__ int c_xt[10] = {0, 0, 0, 0, 1, 1, 1, 2, 2, 3};
__constant__ int c_yt[10] = {0, 1, 2, 3, 1, 2, 3, 2, 3, 3};

__device__ void span_body(const int* __restrict__ seq_len, int t, int b,
                          __nv_bfloat16* As, __nv_bfloat16* Bs, float* red) {
    int x0 = c_xt[t] * 64, y0 = c_yt[t] * 64;
    int slot = b * 10 + t;
    int sl = seq_len[b];
    int tid = threadIdx.x;
    if (y0 > sl) {
        if (tid == 0) { g_span_sum[slot] = 0.f; g_span_cnt2[slot] = 0.f; }
        return;
    }
    float acc[2][2][4] = {};
    mma_nt_loop<64, 64, 2, 2, NSTG>(g_Tb + (size_t)b * Ln * Dn, 1024, x0,
                                    g_reprs_b + (size_t)b * Ln * Dn, 1024, y0, 0, 1024, acc, As, Bs);
    int lane = tid & 31, warp = tid >> 5;
    int wm = warp >> 2, wn = warp & 3, g = lane >> 2, tg = lane & 3;
    float lsum = 0.f, lcnt = 0.f;
    #pragma unroll
    for (int mi = 0; mi < 2; mi++) {
        int xA = x0 + wm * 32 + mi * 16 + g;
        int xB = xA + 8;
        float tbA = g_Tbias[b * Ln + xA];
        float tbB = g_Tbias[b * Ln + xB];
        #pragma unroll
        for (int ni = 0; ni < 2; ni++) {
            int y = y0 + wn * 16 + ni * 8 + 2 * tg;
            #pragma unroll
            for (int e = 0; e < 4; e++) {
                int yy = y + (e & 1);
                int xx = (e < 2) ? xA : xB;
                float tb = (e < 2) ? tbA : tbB;
                if (yy > xx && yy <= sl) {
                    float s = acc[mi][ni][e] + tb;
                    lsum += fmaxf(s, 0.f) + log1pf(expf(-fabsf(s)));
                    int idx = (b << 16) | (xx << 8) | yy;
                    if ((g_bitmap[idx >> 5] >> (idx & 31)) & 1u) lsum -= s;
                    lcnt += 1.f;
                }
            }
        }
    }
    red[tid] = lsum; __syncthreads();
    for (int s = 128; s > 0; s >>= 1) { if (tid < s) red[tid] += red[tid + s]; __syncthreads(); }
    float tot = red[0]; __syncthreads();
    red[tid] = lcnt; __syncthreads();
    for (int s = 128; s > 0; s >>= 1) { if (tid < s) red[tid] += red[tid + s]; __syncthreads(); }
    if (tid == 0) { g_span_sum[slot] = tot; g_span_cnt2[slot] = red[0]; }
}

__device__ void h1_body(int n_t, int m_t, int ks, __nv_bfloat16* As, __nv_bfloat16* Bs) {
    float acc[4][4][4] = {};
    int n0 = n_t * 128, m0 = m_t * 128;
    mma_nt_loop<128, 128, 4, 4, NSTG>(g_goldb, 2048, m0, g_Wp1b, 2048, n0,
                                      ks * 256, ks * 256 + 256, acc, As, Bs);
    int lane = threadIdx.x & 31, warp = threadIdx.x >> 5;
    int wm = warp >> 2, wn = warp & 3, g = lane >> 2, tg = lane & 3;
    float* dst = g_h1p + (size_t)ks * 512 * 256;
    #pragma unroll
    for (int mi = 0; mi < 4; mi++) {
        int m = m0 + wm * 64 + mi * 16 + g;
        #pragma unroll
        for (int ni = 0; ni < 4; ni++) {
            int n = n0 + wn * 32 + ni * 8 + 2 * tg;
            *reinterpret_cast<float2*>(dst + (size_t)m * 256 + n) =
                make_float2(acc[mi][ni][0], acc[mi][ni][1]);
            *reinterpret_cast<float2*>(dst + (size_t)(m + 8) * 256 + n) =
                make_float2(acc[mi][ni][2], acc[mi][ni][3]);
        }
    }
}

// ---- stage2: span (80) | h1 (64) = 144 blocks, one wave ----
__global__ __launch_bounds__(256) void k_stage2(const int* __restrict__ seq_len) {
    extern __shared__ __align__(16) __nv_bfloat16 dyn[];
    __shared__ float red[256];
    int bx = blockIdx.x;
    if (bx < 80) {
        span_body(seq_len, bx % 10, bx / 10, dyn, dyn + NSTG * 64 * 32, red);
    } else {
        int idx = bx - 80;          // (n_t:2, m_t:4, ks:8)
        h1_body(idx & 1, (idx >> 1) & 3, idx >> 3, dyn, dyn + NSTG * 128 * 32);
    }
}

// fused tail: LN(relu) + h2 + logits + warp-softmax CE.  128 blocks x 4 rows.
__global__ __launch_bounds__(256) void k_tail(const float* __restrict__ bp1,
                                              const float* __restrict__ gamma,
                                              const float* __restrict__ beta,
                                              const float* __restrict__ Wp2,
                                              const float* __restrict__ bp2,
                                              const float* __restrict__ lab,
                                              const int* __restrict__ chart,
                                              const int* __restrict__ action_len) {
    __shared__ float h[4][256];
    __shared__ float h2s[4][256];
    __shared__ float lg[4][128];
    int tid = threadIdx.x;
    int r0 = blockIdx.x * 4;
    int warp = tid >> 5, lane = tid & 31;

    // --- LN: warps 0-3, warp r handles row r0+r, lane covers 8 cols ---
    if (warp < 4) {
        int row = r0 + warp;
        int c0 = lane * 8;
        float x[8];
        #pragma unroll
        for (int j = 0; j < 8; j++) x[j] = bp1[c0 + j];
        #pragma unroll
        for (int p = 0; p < 8; p++) {
            const float* src = g_h1p + ((size_t)p * 512 + row) * 256 + c0;
            float4 v0 = *reinterpret_cast<const float4*>(src);
            float4 v1 = *reinterpret_cast<const float4*>(src + 4);
            x[0] += v0.x; x[1] += v0.y; x[2] += v0.z; x[3] += v0.w;
            x[4] += v1.x; x[5] += v1.y; x[6] += v1.z; x[7] += v1.w;
        }
        float sum = 0.f;
        #pragma unroll
        for (int j = 0; j < 8; j++) sum += x[j];
        #pragma unroll
        for (int o = 16; o; o >>= 1) sum += __shfl_xor_sync(0xffffffff, sum, o);
        float mean = sum * (1.0f / En);
        float s2 = 0.f;
        #pragma unroll
        for (int j = 0; j < 8; j++) { x[j] -= mean; s2 += x[j] * x[j]; }
        #pragma unroll
        for (int o = 16; o; o >>= 1) s2 += __shfl_xor_sync(0xffffffff, s2, o);
        float inv = rsqrtf(s2 * (1.0f / En) + 1e-5f);
        #pragma unroll
        for (int j = 0; j < 8; j++) {
            float y = x[j] * inv * gamma[c0 + j] + beta[c0 + j];
            h[warp][c0 + j] = fmaxf(y, 0.f);
        }
    }
    __syncthreads();

    // --- h2[r][tid] = h[r] . Wp2[tid] + bp2[tid], unroll-8 on the Wp2 stream ---
    {
        float acc[4] = {0, 0, 0, 0};
        const float4* wr = reinterpret_cast<const float4*>(Wp2 + (size_t)tid * 256);
        #pragma unroll 8
        for (int k = 0; k < 64; k++) {
            float4 w = wr[k];
            #pragma unroll
            for (int r = 0; r < 4; r++) {
                float4 hv = *reinterpret_cast<const float4*>(&h[r][4 * k]);
                acc[r] += w.x * hv.x + w.y * hv.y + w.z * hv.z + w.w * hv.w;
            }
        }
        float bb = bp2[tid];
        #pragma unroll
        for (int r = 0; r < 4; r++) h2s[r][tid] = acc[r] + bb;
    }
    __syncthreads();

    // --- logits: all 256 threads; t<128 -> rows 0..1 col t; t>=128 -> rows 2..3 col t-128 ---
    {
        int col = tid & 127;
        int rb = (tid >> 7) * 2;
        float acc[2] = {0, 0};
        const float4* lr = reinterpret_cast<const float4*>(lab + (size_t)col * 256);
        #pragma unroll 8
        for (int k = 0; k < 64; k++) {
            float4 w = lr[k];
            #pragma unroll
            for (int r = 0; r < 2; r++) {
                float4 hv = *reinterpret_cast<const float4*>(&h2s[rb + r][4 * k]);
                acc[r] += w.x * hv.x + w.y * hv.y + w.z * hv.z + w.w * hv.w;
            }
        }
        #pragma unroll
        for (int r = 0; r < 2; r++) lg[rb + r][col] = acc[r];
    }
    __syncthreads();

    // --- softmax + CE: warps 0-3, warp r handles row r0+r, shuffle reductions only ---
    if (warp < 4) {
        int r = warp;
        int row = r0 + r;
        float v0 = lg[r][lane], v1 = lg[r][lane + 32];
        float v2 = lg[r][lane + 64], v3 = lg[r][lane + 96];
        float mx = fmaxf(fmaxf(v0, v1), fmaxf(v2, v3));
        #pragma unroll
        for (int o = 16; o; o >>= 1) mx = fmaxf(mx, __shfl_xor_sync(0xffffffff, mx, o));
        float sum = expf(v0 - mx) + expf(v1 - mx) + expf(v2 - mx) + expf(v3 - mx);
        #pragma unroll
        for (int o = 16; o; o >>= 1) sum += __shfl_xor_sync(0xffffffff, sum, o);
        if (lane == 0) {
            float lse = logf(sum);
            int c = chart[row];
            float ce = -(lg[r][c] - mx - lse);
            int b = row >> 6, a = row & 63;
            g_ce_part[row] = (a < action_len[b]) ? ce : 0.f;
        }
    }
}

// final deterministic reduction
__global__ __launch_bounds__(512) void k_final(const int* __restrict__ action_len,
                                               float* __restrict__ out) {
    __shared__ float red[512];
    int tid = threadIdx.x;
    red[tid] = (tid < 80 ? g_span_sum[tid] : 0.f); __syncthreads();
    for (int s = 256; s > 0; s >>= 1) { if (tid < s) red[tid] += red[tid + s]; __syncthreads(); }
    float span_num = red[0]; __syncthreads();

    red[tid] = (tid < 80 ? g_span_cnt2[tid] : 0.f); __syncthreads();
    for (int s = 256; s > 0; s >>= 1) { if (tid < s) red[tid] += red[tid + s]; __syncthreads(); }
    float span_cnt = red[0]; __syncthreads();

    red[tid] = g_ce_part[tid]; __syncthreads();
    for (int s = 256; s > 0; s >>= 1) { if (tid < s) red[tid] += red[tid + s]; __syncthreads(); }
    float ce_sum = red[0];

    if (tid == 0) {
        int lc = 0;
        for (int b = 0; b < Bn; b++) lc += action_len[b];
        out[0] = span_num / span_cnt + ce_sum / (float)lc;
    }
}

// ===================== launch =====================
extern "C" void kernel_launch(void* const* d_in, const int* in_sizes, int n_in,
                              void* d_out, int out_size) {
    const float* reprs      = (const float*)d_in[0];
    const float* word_repr  = (const float*)d_in[1];
    const int*   seq_len    = (const int*)d_in[2];
    const int*   gold_span  = (const int*)d_in[3];
    const int*   span_start = (const int*)d_in[4];
    const int*   span_end   = (const int*)d_in[5];
    const int*   chart      = (const int*)d_in[6];
    const int*   action_len = (const int*)d_in[7];
    const float* Wb         = (const float*)d_in[8];
    const float* Wp1        = (const float*)d_in[9];
    const float* bp1        = (const float*)d_in[10];
    const float* gamma      = (const float*)d_in[11];
    const float* beta       = (const float*)d_in[12];
    const float* Wp2        = (const float*)d_in[13];
    const float* bp2        = (const float*)d_in[14];
    const float* lab        = (const float*)d_in[15];
    float* out = (float*)d_out;

    static bool attr_done = false;
    if (!attr_done) {
        cudaFuncSetAttribute(k_stage1, cudaFuncAttributeMaxDynamicSharedMemorySize, DYN_SMEM_128);
        cudaFuncSetAttribute(k_stage2, cudaFuncAttributeMaxDynamicSharedMemorySize, DYN_SMEM_128);
        attr_done = true;
    }

    // L0: conversions + W^T + bias column + bitmap zero
    k_prelude<<<CV_BLOCKS + WT_BLOCKS + 64 + 8, 256>>>(reprs, word_repr, Wp1, Wb);
    // L1: gemm1 || gold_repr || setbits
    k_stage1<<<648, 256, DYN_SMEM_128>>>(Wb, reprs, span_start, span_end, gold_span);
    // L2: span (64x64, 80 tiles) || h1 split-K=8
    k_stage2<<<144, 256, DYN_SMEM_128>>>(seq_len);
    // L3: fused LN + projector + CE (128 blocks x 4 rows)
    k_tail<<<128, 256>>>(bp1, gamma, beta, Wp2, bp2, lab, chart, action_len);
    // L4: final reduction
    k_final<<<1, 512>>>(action_len, out);
}